// round 11
// baseline (speedup 1.0000x reference)
#include <cuda_runtime.h>
#include <math.h>

// ---------------- problem constants ----------------
#define BB      4
#define SS      4096
#define DM      1024
#define HH      16
#define HDIM    64
#define DCC     512
#define KSLOT   64
#define MCACHE  768          // L*K = 12*64
#define TT      256          // min(S, 4K)
#define DFF     4096
#define LAYER_OFF 192        // LAYER*K = 3*64
#define NROWS   (BB*SS)      // 16384
#define SCALE_DC 0.044194173824159216f   // 1/sqrt(512)

// ---------------- scratch (static device memory; allocation-free) ----------------
__device__ float g_qr    [(size_t)NROWS*DCC];
__device__ float g_scores[(size_t)NROWS*MCACHE];
__device__ float g_ctx   [(size_t)NROWS*DCC];
__device__ float g_gate  [(size_t)NROWS];
__device__ float g_fused [(size_t)NROWS*DM];
__device__ float g_pq    [(size_t)NROWS*DM];
__device__ float g_pk    [(size_t)NROWS*DM];
__device__ float g_v     [(size_t)NROWS*DM];
__device__ float g_kv    [(size_t)BB*HH*HDIM*HDIM];
__device__ float g_ksum  [(size_t)BB*HH*HDIM];
__device__ float g_attn  [(size_t)NROWS*DM];
__device__ float g_z     [(size_t)NROWS*DM];
__device__ float g_x1    [(size_t)NROWS*DM];
__device__ float g_h     [(size_t)NROWS*DM];
__device__ float g_t1    [(size_t)NROWS*DFF];
__device__ float g_z2    [(size_t)NROWS*DM];
__device__ float g_wproj [(size_t)BB*TT*DCC];
__device__ float g_vals  [(size_t)BB*TT*DCC];
__device__ float g_wgate [(size_t)BB*TT];
__device__ float g_p     [(size_t)BB*TT*KSLOT];

// ---------------- generic SGEMM: 128x128x8, 8x8/thread, 256 threads ----------------
#define BM 128
#define BN 128
#define BKK 8

enum { EPI_NONE=0, EPI_ELU1=1, EPI_GATEADD=2, EPI_ADD=3, EPI_BIAS_GELU=4, EPI_BIAS_ADD=5 };

template<int EPI, bool TB>
__global__ __launch_bounds__(256) void sgemm_kernel(
    const float* __restrict__ A, const float* __restrict__ B, float* __restrict__ C,
    int M, int N, int K,
    long sA, long sB, long sC,
    const float* __restrict__ bias,
    const float* __restrict__ add, long sAdd,
    const float* __restrict__ gate)
{
    __shared__ float As[BKK][BM];
    __shared__ float Bs[BKK][BN];

    const int bz = blockIdx.z;
    A += (long)bz * sA;
    B += (long)bz * sB;
    C += (long)bz * sC;
    if (EPI==EPI_GATEADD || EPI==EPI_ADD || EPI==EPI_BIAS_ADD) add += (long)bz * sAdd;

    const long bm = (long)blockIdx.y * BM;
    const long bn = (long)blockIdx.x * BN;
    const int tid = threadIdx.x;

    const int lr = tid >> 1;            // 0..127 (A / transposed-B row)
    const int lc = (tid & 1) * 4;       // 0 or 4
    const int br = tid >> 5;            // 0..7   (B NN row)
    const int bc = (tid & 31) * 4;      // 0..124

    const int ty = tid >> 4;            // 0..15
    const int tx = tid & 15;            // 0..15

    float acc[8][8];
    #pragma unroll
    for (int i = 0; i < 8; i++)
        #pragma unroll
        for (int j = 0; j < 8; j++) acc[i][j] = 0.f;

    for (int k0 = 0; k0 < K; k0 += BKK) {
        float4 av = *(const float4*)(A + (bm + lr) * (long)K + k0 + lc);
        As[lc+0][lr] = av.x; As[lc+1][lr] = av.y; As[lc+2][lr] = av.z; As[lc+3][lr] = av.w;
        if (!TB) {
            *(float4*)&Bs[br][bc] = *(const float4*)(B + (long)(k0 + br) * N + bn + bc);
        } else {
            float4 bv = *(const float4*)(B + (bn + lr) * (long)K + k0 + lc);
            Bs[lc+0][lr] = bv.x; Bs[lc+1][lr] = bv.y; Bs[lc+2][lr] = bv.z; Bs[lc+3][lr] = bv.w;
        }
        __syncthreads();

        #pragma unroll
        for (int k = 0; k < BKK; k++) {
            float ra[8], rb[8];
            #pragma unroll
            for (int i = 0; i < 8; i++) ra[i] = As[k][ty*8 + i];
            #pragma unroll
            for (int j = 0; j < 8; j++) rb[j] = Bs[k][tx*8 + j];
            #pragma unroll
            for (int i = 0; i < 8; i++)
                #pragma unroll
                for (int j = 0; j < 8; j++)
                    acc[i][j] = fmaf(ra[i], rb[j], acc[i][j]);
        }
        __syncthreads();
    }

    #pragma unroll
    for (int i = 0; i < 8; i++) {
        long row = bm + ty*8 + i;
        float grow = 0.f;
        if (EPI == EPI_GATEADD) grow = gate[row];
        #pragma unroll
        for (int j = 0; j < 8; j++) {
            long col = bn + tx*8 + j;
            float v = acc[i][j];
            float o;
            if (EPI == EPI_NONE) {
                o = v;
            } else if (EPI == EPI_ELU1) {
                o = (v > 0.f) ? (v + 1.f) : expf(v);
            } else if (EPI == EPI_GATEADD) {
                o = add[row * (long)N + col] + grow * v;
            } else if (EPI == EPI_ADD) {
                o = v + add[row * (long)N + col];
            } else if (EPI == EPI_BIAS_GELU) {
                float t = v + bias[col];
                o = 0.5f * t * (1.f + erff(t * 0.70710678118654752f));
            } else { // EPI_BIAS_ADD
                o = v + bias[col] + add[row * (long)N + col];
            }
            C[row * (long)N + col] = o;
        }
    }
}

// ---------------- row dot + sigmoid (read/write gates) ----------------
__global__ void rowgate_kernel(const float* __restrict__ X, long batchStride, int rowsPerBatch,
                               const float* __restrict__ W, const float* __restrict__ bsc,
                               float* __restrict__ out)
{
    int row = blockIdx.x;
    int b = row / rowsPerBatch;
    int t = row - b * rowsPerBatch;
    const float4* xr = (const float4*)(X + (long)b * batchStride + (long)t * DM);
    const float4* w4 = (const float4*)W;
    int tid = threadIdx.x;
    float4 a = xr[tid], w = w4[tid];
    float s = a.x*w.x + a.y*w.y + a.z*w.z + a.w*w.w;
    __shared__ float red[256];
    red[tid] = s; __syncthreads();
    for (int o = 128; o > 0; o >>= 1) { if (tid < o) red[tid] += red[tid + o]; __syncthreads(); }
    if (tid == 0) out[row] = 1.f / (1.f + expf(-(red[0] + bsc[0])));
}

// ---------------- softmax over 768 (with 1/sqrt(DC) scale) ----------------
__global__ void softmax768_kernel(float* __restrict__ s)
{
    long row = blockIdx.x;
    float* p = s + row * (long)MCACHE;
    int tid = threadIdx.x;
    __shared__ float red[256];
    float v0 = p[tid]       * SCALE_DC;
    float v1 = p[tid + 256] * SCALE_DC;
    float v2 = p[tid + 512] * SCALE_DC;
    float m = fmaxf(v0, fmaxf(v1, v2));
    red[tid] = m; __syncthreads();
    for (int o = 128; o > 0; o >>= 1) { if (tid < o) red[tid] = fmaxf(red[tid], red[tid+o]); __syncthreads(); }
    m = red[0]; __syncthreads();
    v0 = expf(v0 - m); v1 = expf(v1 - m); v2 = expf(v2 - m);
    red[tid] = v0 + v1 + v2; __syncthreads();
    for (int o = 128; o > 0; o >>= 1) { if (tid < o) red[tid] += red[tid+o]; __syncthreads(); }
    float inv = 1.f / red[0];
    p[tid] = v0 * inv; p[tid + 256] = v1 * inv; p[tid + 512] = v2 * inv;
}

// ---------------- linear attention: kv = pk^T v, ksum = sum pk (per b,h) ----------------
__global__ void kv_kernel(const float* __restrict__ pk, const float* __restrict__ v,
                          float* __restrict__ kvout, float* __restrict__ ksout)
{
    int bh = blockIdx.x;
    int b = bh / HH, h = bh % HH;
    const long baseoff = ((long)b * SS) * DM + (long)h * HDIM;
    __shared__ float pks[32][64];
    __shared__ float vs[32][64];
    int tid = threadIdx.x;
    int d0 = (tid >> 4) * 4;
    int e0 = (tid & 15) * 4;
    float acc[4][4];
    #pragma unroll
    for (int i=0;i<4;i++) { acc[i][0]=0;acc[i][1]=0;acc[i][2]=0;acc[i][3]=0; }
    float ks[4] = {0,0,0,0};
    int f0 = tid * 2;

    for (int s0 = 0; s0 < SS; s0 += 32) {
        #pragma unroll
        for (int i = 0; i < 2; i++) {
            int f = f0 + i;             // 0..511
            int r = f >> 4;             // 0..31
            int c = (f & 15) * 4;       // 0..60
            long g = baseoff + (long)(s0 + r) * DM + c;
            *(float4*)&pks[r][c] = *(const float4*)(pk + g);
            *(float4*)&vs[r][c]  = *(const float4*)(v  + g);
        }
        __syncthreads();
        #pragma unroll 8
        for (int s = 0; s < 32; s++) {
            float4 pv = *(const float4*)&pks[s][d0];
            float4 vv = *(const float4*)&vs[s][e0];
            float pa[4] = {pv.x, pv.y, pv.z, pv.w};
            float va[4] = {vv.x, vv.y, vv.z, vv.w};
            #pragma unroll
            for (int i = 0; i < 4; i++)
                #pragma unroll
                for (int j = 0; j < 4; j++)
                    acc[i][j] = fmaf(pa[i], va[j], acc[i][j]);
            if (e0 == 0) {
                #pragma unroll
                for (int i = 0; i < 4; i++) ks[i] += pa[i];
            }
        }
        __syncthreads();
    }

    float* kvb = kvout + (long)bh * HDIM * HDIM;
    #pragma unroll
    for (int i = 0; i < 4; i++)
        #pragma unroll
        for (int j = 0; j < 4; j++)
            kvb[(d0 + i) * 64 + e0 + j] = acc[i][j];
    if (e0 == 0) {
        float* ksb = ksout + (long)bh * HDIM;
        #pragma unroll
        for (int i = 0; i < 4; i++) ksb[d0 + i] = ks[i];
    }
}

// ---------------- linear attention: attn = (pq @ kv) / (pq·ksum + eps) ----------------
__global__ void numden_kernel(const float* __restrict__ pq, const float* __restrict__ kv,
                              const float* __restrict__ ksum, float* __restrict__ attn)
{
    int bh = blockIdx.x;
    int b = bh / HH, h = bh % HH;
    __shared__ float kvs[64*64];
    __shared__ float kss[64];
    int tid = threadIdx.x;
    {
        const float4* kvb = (const float4*)(kv + (long)bh * 4096);
        for (int i = tid; i < 1024; i += 256) ((float4*)kvs)[i] = kvb[i];
        if (tid < 16) ((float4*)kss)[tid] = ((const float4*)(ksum + (long)bh * 64))[tid];
    }
    __syncthreads();

    int srow = blockIdx.y * 128 + (tid >> 1);
    int e0 = (tid & 1) * 32;
    const float* qr = pq + ((long)b * SS + srow) * DM + (long)h * HDIM;
    float num[32];
    #pragma unroll
    for (int e = 0; e < 32; e++) num[e] = 0.f;
    float den = 0.f;

    #pragma unroll
    for (int d4 = 0; d4 < 16; d4++) {
        float4 qv = *(const float4*)(qr + d4 * 4);
        float qa[4] = {qv.x, qv.y, qv.z, qv.w};
        #pragma unroll
        for (int dd = 0; dd < 4; dd++) {
            int d = d4 * 4 + dd;
            den = fmaf(qa[dd], kss[d], den);
            const float* kr = &kvs[d * 64 + e0];
            #pragma unroll
            for (int e = 0; e < 32; e++) num[e] = fmaf(qa[dd], kr[e], num[e]);
        }
    }
    float inv = 1.f / (den + 1e-6f);
    float* o = attn + ((long)b * SS + srow) * DM + (long)h * HDIM + e0;
    #pragma unroll
    for (int e = 0; e < 32; e++) o[e] = num[e] * inv;
}

// ---------------- fused double LayerNorm: x1 = LN(z;n1), h = LN(x1;ln0) ----------------
__global__ void double_ln_kernel(const float* __restrict__ z,
    const float* __restrict__ g1, const float* __restrict__ b1,
    const float* __restrict__ g0, const float* __restrict__ b0,
    float* __restrict__ x1, float* __restrict__ h)
{
    long row = blockIdx.x;
    int tid = threadIdx.x;
    __shared__ float red[256];
    float4 v = ((const float4*)(z + row * (long)DM))[tid];

    float s = v.x + v.y + v.z + v.w;
    red[tid] = s; __syncthreads();
    for (int o = 128; o > 0; o >>= 1) { if (tid < o) red[tid] += red[tid+o]; __syncthreads(); }
    float m = red[0] * (1.f/1024.f); __syncthreads();
    float dx = v.x-m, dy = v.y-m, dz = v.z-m, dw = v.w-m;
    red[tid] = dx*dx + dy*dy + dz*dz + dw*dw; __syncthreads();
    for (int o = 128; o > 0; o >>= 1) { if (tid < o) red[tid] += red[tid+o]; __syncthreads(); }
    float rstd = rsqrtf(red[0] * (1.f/1024.f) + 1e-5f); __syncthreads();

    float4 g = ((const float4*)g1)[tid];
    float4 bb = ((const float4*)b1)[tid];
    float4 o1;
    o1.x = g.x * dx * rstd + bb.x;
    o1.y = g.y * dy * rstd + bb.y;
    o1.z = g.z * dz * rstd + bb.z;
    o1.w = g.w * dw * rstd + bb.w;
    ((float4*)(x1 + row * (long)DM))[tid] = o1;

    // second LN over x1
    float s2 = o1.x + o1.y + o1.z + o1.w;
    red[tid] = s2; __syncthreads();
    for (int o = 128; o > 0; o >>= 1) { if (tid < o) red[tid] += red[tid+o]; __syncthreads(); }
    float m2 = red[0] * (1.f/1024.f); __syncthreads();
    float ex = o1.x-m2, ey = o1.y-m2, ez = o1.z-m2, ew = o1.w-m2;
    red[tid] = ex*ex + ey*ey + ez*ez + ew*ew; __syncthreads();
    for (int o = 128; o > 0; o >>= 1) { if (tid < o) red[tid] += red[tid+o]; __syncthreads(); }
    float rstd2 = rsqrtf(red[0] * (1.f/1024.f) + 1e-5f); __syncthreads();

    float4 gg = ((const float4*)g0)[tid];
    float4 b2v = ((const float4*)b0)[tid];
    float4 o2;
    o2.x = gg.x * ex * rstd2 + b2v.x;
    o2.y = gg.y * ey * rstd2 + b2v.y;
    o2.z = gg.z * ez * rstd2 + b2v.z;
    o2.w = gg.w * ew * rstd2 + b2v.w;
    ((float4*)(h + row * (long)DM))[tid] = o2;
}

// ---------------- single LayerNorm (final y) ----------------
__global__ void final_ln_kernel(const float* __restrict__ z,
    const float* __restrict__ g, const float* __restrict__ b,
    float* __restrict__ y)
{
    long row = blockIdx.x;
    int tid = threadIdx.x;
    __shared__ float red[256];
    float4 v = ((const float4*)(z + row * (long)DM))[tid];
    red[tid] = v.x + v.y + v.z + v.w; __syncthreads();
    for (int o = 128; o > 0; o >>= 1) { if (tid < o) red[tid] += red[tid+o]; __syncthreads(); }
    float m = red[0] * (1.f/1024.f); __syncthreads();
    float dx = v.x-m, dy = v.y-m, dz = v.z-m, dw = v.w-m;
    red[tid] = dx*dx + dy*dy + dz*dz + dw*dw; __syncthreads();
    for (int o = 128; o > 0; o >>= 1) { if (tid < o) red[tid] += red[tid+o]; __syncthreads(); }
    float rstd = rsqrtf(red[0] * (1.f/1024.f) + 1e-5f);

    float4 gv = ((const float4*)g)[tid];
    float4 bv = ((const float4*)b)[tid];
    float4 o;
    o.x = gv.x * dx * rstd + bv.x;
    o.y = gv.y * dy * rstd + bv.y;
    o.z = gv.z * dz * rstd + bv.z;
    o.w = gv.w * dw * rstd + bv.w;
    ((float4*)(y + row * (long)DM))[tid] = o;
}

// ---------------- write path: slot logits + softmax + gate -> p ----------------
__global__ void slot_kernel(const float* __restrict__ wproj, const float* __restrict__ cache,
                            const float* __restrict__ wgate, float* __restrict__ p)
{
    int blk = blockIdx.x;
    int b = blk >> 8;           // TT = 256
    int t = blk & 255;
    int k = threadIdx.x;        // 0..63
    const float4* wp = (const float4*)(wproj + ((long)b * TT + t) * DCC);
    const float4* lr = (const float4*)(cache + ((long)b * MCACHE + LAYER_OFF + k) * DCC);
    float dot = 0.f;
    #pragma unroll 8
    for (int c = 0; c < 128; c++) {
        float4 a = wp[c], w = lr[c];
        dot += a.x*w.x + a.y*w.y + a.z*w.z + a.w*w.w;
    }
    float logit = dot * SCALE_DC;
    __shared__ float red[64];
    red[k] = logit; __syncthreads();
    for (int o = 32; o > 0; o >>= 1) { if (k < o) red[k] = fmaxf(red[k], red[k+o]); __syncthreads(); }
    float m = red[0]; __syncthreads();
    float e = expf(logit - m);
    red[k] = e; __syncthreads();
    for (int o = 32; o > 0; o >>= 1) { if (k < o) red[k] += red[k+o]; __syncthreads(); }
    float val = e / red[0] * wgate[b * TT + t];
    p[((long)b * TT + t) * KSLOT + k] = val;
}

// ---------------- write path: out_cache[slice] += p^T vals ----------------
__global__ void update_kernel(const float* __restrict__ p, const float* __restrict__ vals,
                              float* __restrict__ out_cache)
{
    int blk = blockIdx.x;
    int b = blk >> 6;
    int k = blk & 63;
    int c0 = threadIdx.x * 2;
    float a0 = 0.f, a1 = 0.f;
    for (int t = 0; t < TT; t++) {
        float pv = p[((long)b * TT + t) * KSLOT + k];
        const float* vr = vals + ((long)b * TT + t) * DCC;
        a0 = fmaf(pv, vr[c0],     a0);
        a1 = fmaf(pv, vr[c0 + 1], a1);
    }
    float* oc = out_cache + ((long)b * MCACHE + LAYER_OFF + k) * DCC;
    oc[c0]     += a0;
    oc[c0 + 1] += a1;
}

// ---------------- launch ----------------
extern "C" void kernel_launch(void* const* d_in, const int* in_sizes, int n_in,
                              void* d_out_, int out_size)
{
    const float* x     = (const float*)d_in[0];
    const float* cache = (const float*)d_in[1];
    const float* Wq_r  = (const float*)d_in[2];
    const float* Wo_r  = (const float*)d_in[3];
    const float* Wg_r  = (const float*)d_in[4];
    const float* bg_r  = (const float*)d_in[5];
    const float* Wq    = (const float*)d_in[6];
    const float* Wk    = (const float*)d_in[7];
    const float* Wv    = (const float*)d_in[8];
    const float* Wo    = (const float*)d_in[9];
    const float* ln0g  = (const float*)d_in[10];
    const float* ln0b  = (const float*)d_in[11];
    const float* W1    = (const float*)d_in[12];
    const float* b1    = (const float*)d_in[13];
    const float* W2    = (const float*)d_in[14];
    const float* b2    = (const float*)d_in[15];
    const float* n1g   = (const float*)d_in[16];
    const float* n1b   = (const float*)d_in[17];
    const float* n2g   = (const float*)d_in[18];
    const float* n2b   = (const float*)d_in[19];
    /* d_in[20] = Ws : computed-but-unused in reference (write_scores) */
    const float* Wgw   = (const float*)d_in[21];
    const float* bgw   = (const float*)d_in[22];
    const float* Wslot = (const float*)d_in[23];
    const float* Wvw   = (const float*)d_in[24];

    float* out       = (float*)d_out_;
    float* y_out     = out;                                   // B*S*D
    float* cache_out = out + (size_t)NROWS * DM;              // B*MCACHE*DCC

    // resolve scratch symbols (host-side only; not part of the captured graph)
    float *p_qr, *p_scores, *p_ctx, *p_gate, *p_fused, *p_pq, *p_pk, *p_v;
    float *p_kv, *p_ksum, *p_attn, *p_z, *p_x1, *p_h, *p_t1, *p_z2;
    float *p_wproj, *p_vals, *p_wgate, *p_p;
    cudaGetSymbolAddress((void**)&p_qr,     g_qr);
    cudaGetSymbolAddress((void**)&p_scores, g_scores);
    cudaGetSymbolAddress((void**)&p_ctx,    g_ctx);
    cudaGetSymbolAddress((void**)&p_gate,   g_gate);
    cudaGetSymbolAddress((void**)&p_fused,  g_fused);
    cudaGetSymbolAddress((void**)&p_pq,     g_pq);
    cudaGetSymbolAddress((void**)&p_pk,     g_pk);
    cudaGetSymbolAddress((void**)&p_v,      g_v);
    cudaGetSymbolAddress((void**)&p_kv,     g_kv);
    cudaGetSymbolAddress((void**)&p_ksum,   g_ksum);
    cudaGetSymbolAddress((void**)&p_attn,   g_attn);
    cudaGetSymbolAddress((void**)&p_z,      g_z);
    cudaGetSymbolAddress((void**)&p_x1,     g_x1);
    cudaGetSymbolAddress((void**)&p_h,      g_h);
    cudaGetSymbolAddress((void**)&p_t1,     g_t1);
    cudaGetSymbolAddress((void**)&p_z2,     g_z2);
    cudaGetSymbolAddress((void**)&p_wproj,  g_wproj);
    cudaGetSymbolAddress((void**)&p_vals,   g_vals);
    cudaGetSymbolAddress((void**)&p_wgate,  g_wgate);
    cudaGetSymbolAddress((void**)&p_p,      g_p);

    const long ZL = 0;

    // read gate: sigmoid(x @ Wg_r + bg_r)
    rowgate_kernel<<<NROWS, 256>>>(x, ZL, NROWS, Wg_r, bg_r, p_gate);

    // q_r = x @ Wq_r          [16384 x 512]
    sgemm_kernel<EPI_NONE,false><<<dim3(DCC/BN, NROWS/BM, 1), 256>>>(
        x, Wq_r, p_qr, NROWS, DCC, DM, ZL, ZL, ZL, nullptr, nullptr, ZL, nullptr);

    // scores = q_r @ cache^T  (batched NT)  [4 x 4096 x 768]
    sgemm_kernel<EPI_NONE,true><<<dim3(MCACHE/BN, SS/BM, BB), 256>>>(
        p_qr, cache, p_scores, SS, MCACHE, DCC,
        (long)SS*DCC, (long)MCACHE*DCC, (long)SS*MCACHE, nullptr, nullptr, ZL, nullptr);

    // softmax(scores / sqrt(DC))
    softmax768_kernel<<<NROWS, 256>>>(p_scores);

    // ctx = attn @ cache      (batched NN)  [4 x 4096 x 512]
    sgemm_kernel<EPI_NONE,false><<<dim3(DCC/BN, SS/BM, BB), 256>>>(
        p_scores, cache, p_ctx, SS, DCC, MCACHE,
        (long)SS*MCACHE, (long)MCACHE*DCC, (long)SS*DCC, nullptr, nullptr, ZL, nullptr);

    // fused = x + gate * (ctx @ Wo_r)
    sgemm_kernel<EPI_GATEADD,false><<<dim3(DM/BN, NROWS/BM, 1), 256>>>(
        p_ctx, Wo_r, p_fused, NROWS, DM, DCC, ZL, ZL, ZL, nullptr, x, ZL, p_gate);

    // pq = elu(fused @ Wq)+1, pk = elu(fused @ Wk)+1, v = fused @ Wv
    sgemm_kernel<EPI_ELU1,false><<<dim3(DM/BN, NROWS/BM, 1), 256>>>(
        p_fused, Wq, p_pq, NROWS, DM, DM, ZL, ZL, ZL, nullptr, nullptr, ZL, nullptr);
    sgemm_kernel<EPI_ELU1,false><<<dim3(DM/BN, NROWS/BM, 1), 256>>>(
        p_fused, Wk, p_pk, NROWS, DM, DM, ZL, ZL, ZL, nullptr, nullptr, ZL, nullptr);
    sgemm_kernel<EPI_NONE,false><<<dim3(DM/BN, NROWS/BM, 1), 256>>>(
        p_fused, Wv, p_v, NROWS, DM, DM, ZL, ZL, ZL, nullptr, nullptr, ZL, nullptr);

    // linear attention
    kv_kernel<<<BB*HH, 256>>>(p_pk, p_v, p_kv, p_ksum);
    numden_kernel<<<dim3(BB*HH, SS/128), 256>>>(p_pq, p_kv, p_ksum, p_attn);

    // z = fused + attn @ Wo
    sgemm_kernel<EPI_ADD,false><<<dim3(DM/BN, NROWS/BM, 1), 256>>>(
        p_attn, Wo, p_z, NROWS, DM, DM, ZL, ZL, ZL, nullptr, p_fused, ZL, nullptr);

    // x1 = LN(z; n1), h = LN(x1; ln0)
    double_ln_kernel<<<NROWS, 256>>>(p_z, n1g, n1b, ln0g, ln0b, p_x1, p_h);

    // t1 = gelu(h @ W1 + b1)
    sgemm_kernel<EPI_BIAS_GELU,false><<<dim3(DFF/BN, NROWS/BM, 1), 256>>>(
        p_h, W1, p_t1, NROWS, DFF, DM, ZL, ZL, ZL, b1, nullptr, ZL, nullptr);

    // z2 = x1 + t1 @ W2 + b2
    sgemm_kernel<EPI_BIAS_ADD,false><<<dim3(DM/BN, NROWS/BM, 1), 256>>>(
        p_t1, W2, p_z2, NROWS, DM, DFF, ZL, ZL, ZL, b2, p_x1, ZL, nullptr);

    // y = LN(z2; n2)  -> straight into d_out
    final_ln_kernel<<<NROWS, 256>>>(p_z2, n2g, n2b, y_out);

    // ---- write path on wc = y[:, :256, :] ----
    // wproj = wc @ Wslot, vals = wc @ Wvw  (batched, A rows strided by S*D per batch)
    sgemm_kernel<EPI_NONE,false><<<dim3(DCC/BN, TT/BM, BB), 256>>>(
        y_out, Wslot, p_wproj, TT, DCC, DM,
        (long)SS*DM, ZL, (long)TT*DCC, nullptr, nullptr, ZL, nullptr);
    sgemm_kernel<EPI_NONE,false><<<dim3(DCC/BN, TT/BM, BB), 256>>>(
        y_out, Wvw, p_vals, TT, DCC, DM,
        (long)SS*DM, ZL, (long)TT*DCC, nullptr, nullptr, ZL, nullptr);

    // write gate
    rowgate_kernel<<<BB*TT, 256>>>(y_out, (long)SS*DM, TT, Wgw, bgw, p_wgate);

    // slot probs * gate
    slot_kernel<<<BB*TT, 64>>>(p_wproj, cache, p_wgate, p_p);

    // new_cache = cache; new_cache[:, layer slice] += p^T vals
    cudaMemcpyAsync(cache_out, cache, (size_t)BB*MCACHE*DCC*sizeof(float),
                    cudaMemcpyDeviceToDevice, 0);
    update_kernel<<<BB*KSLOT, 256>>>(p_p, p_vals, cache_out);
}

// round 12
// speedup vs baseline: 2.8281x; 2.8281x over previous
#include <cuda_runtime.h>
#include <math.h>
#include <stdint.h>

// ---------------- problem constants ----------------
#define BB      4
#define SS      4096
#define DM      1024
#define HH      16
#define HDIM    64
#define DCC     512
#define KSLOT   64
#define MCACHE  768          // L*K = 12*64
#define TT      256          // min(S, 4K)
#define DFF     4096
#define LAYER_OFF 192        // LAYER*K = 3*64
#define NROWS   (BB*SS)      // 16384
#define SCALE_DC 0.044194173824159216f   // 1/sqrt(512)

// ---------------- scratch (static device memory; allocation-free) ----------------
__device__ float g_qr    [(size_t)NROWS*DCC];
__device__ float g_scores[(size_t)NROWS*MCACHE];
__device__ float g_ctx   [(size_t)NROWS*DCC];
__device__ float g_gate  [(size_t)NROWS];
__device__ float g_fused [(size_t)NROWS*DM];
__device__ float g_pq    [(size_t)NROWS*DM];
__device__ float g_pk    [(size_t)NROWS*DM];
__device__ float g_v     [(size_t)NROWS*DM];
__device__ float g_kv    [(size_t)BB*HH*HDIM*HDIM];
__device__ float g_ksum  [(size_t)BB*HH*HDIM];
__device__ float g_attn  [(size_t)NROWS*DM];
__device__ float g_z     [(size_t)NROWS*DM];
__device__ float g_x1    [(size_t)NROWS*DM];
__device__ float g_h     [(size_t)NROWS*DM];
__device__ float g_t1    [(size_t)NROWS*DFF];
__device__ float g_z2    [(size_t)NROWS*DM];
__device__ float g_wproj [(size_t)BB*TT*DCC];
__device__ float g_vals  [(size_t)BB*TT*DCC];
__device__ float g_wgate [(size_t)BB*TT];
__device__ float g_p     [(size_t)BB*TT*KSLOT];

// ---------------- TF32 tensor-core GEMM: 128x128x32, 8 warps, m16n8k8 ----------------
#define BM 128
#define BN 128
#define BKK 32
#define ASTRIDE 40    // BKK + 8  -> bank = (8m + k) % 32, conflict-free both ways
#define BSTRIDE 136   // BN  + 8  -> bank = (8k + n) % 32, conflict-free both ways

enum { EPI_NONE=0, EPI_ELU1=1, EPI_GATEADD=2, EPI_ADD=3, EPI_BIAS_GELU=4, EPI_BIAS_ADD=5 };

__device__ __forceinline__ uint32_t f2tf(float f) {
    uint32_t u;
    asm("cvt.rna.tf32.f32 %0, %1;" : "=r"(u) : "f"(f));
    return u;
}

__device__ __forceinline__ void mma_tf32(float* c, const uint32_t* a, const uint32_t* b) {
    asm("mma.sync.aligned.m16n8k8.row.col.f32.tf32.tf32.f32 "
        "{%0,%1,%2,%3}, {%4,%5,%6,%7}, {%8,%9}, {%0,%1,%2,%3};"
        : "+f"(c[0]), "+f"(c[1]), "+f"(c[2]), "+f"(c[3])
        : "r"(a[0]), "r"(a[1]), "r"(a[2]), "r"(a[3]), "r"(b[0]), "r"(b[1]));
}

template<int EPI, bool TB>
__global__ __launch_bounds__(256, 2) void tgemm_kernel(
    const float* __restrict__ A, const float* __restrict__ B, float* __restrict__ C,
    int M, int N, int K,
    long sA, long sB, long sC,
    const float* __restrict__ bias,
    const float* __restrict__ add, long sAdd,
    const float* __restrict__ gate)
{
    // A tile: [m][k] stride 40.  B tile: TB -> [n][k] stride 40, NN -> [k][n] stride 136.
    __shared__ __align__(16) uint32_t As[BM * ASTRIDE];
    __shared__ __align__(16) uint32_t Bs[TB ? (BN * ASTRIDE) : (BKK * BSTRIDE)];

    const int bz = blockIdx.z;
    A += (long)bz * sA;
    B += (long)bz * sB;
    C += (long)bz * sC;
    if (EPI==EPI_GATEADD || EPI==EPI_ADD || EPI==EPI_BIAS_ADD) add += (long)bz * sAdd;

    const long bm = (long)blockIdx.y * BM;
    const long bn = (long)blockIdx.x * BN;
    const int tid  = threadIdx.x;
    const int lane = tid & 31;
    const int warp = tid >> 5;
    const int wm = warp & 1;        // 2 warps along M  -> 2*64 = 128
    const int wn = warp >> 1;       // 4 warps along N  -> 4*32 = 128
    const int g  = lane >> 2;       // 0..7
    const int t  = lane & 3;        // 0..3

    float acc[4][4][4];
    #pragma unroll
    for (int i = 0; i < 4; i++)
        #pragma unroll
        for (int j = 0; j < 4; j++) {
            acc[i][j][0]=0.f; acc[i][j][1]=0.f; acc[i][j][2]=0.f; acc[i][j][3]=0.f;
        }

    for (int k0 = 0; k0 < K; k0 += BKK) {
        // --- load A tile 128x32 (coalesced float4 along K, STS.128 conflict-free) ---
        #pragma unroll
        for (int it = 0; it < 4; it++) {
            int idx = it * 256 + tid;
            int row = idx >> 3;
            int c4  = (idx & 7) * 4;
            float4 v = *(const float4*)(A + (bm + row) * (long)K + k0 + c4);
            uint4 u = make_uint4(f2tf(v.x), f2tf(v.y), f2tf(v.z), f2tf(v.w));
            *(uint4*)&As[row * ASTRIDE + c4] = u;
        }
        // --- load B tile ---
        if (TB) {
            // B is N x K row-major; tile rows = n
            #pragma unroll
            for (int it = 0; it < 4; it++) {
                int idx = it * 256 + tid;
                int row = idx >> 3;             // n
                int c4  = (idx & 7) * 4;        // k
                float4 v = *(const float4*)(B + (bn + row) * (long)K + k0 + c4);
                uint4 u = make_uint4(f2tf(v.x), f2tf(v.y), f2tf(v.z), f2tf(v.w));
                *(uint4*)&Bs[row * ASTRIDE + c4] = u;
            }
        } else {
            // B is K x N row-major; tile rows = k
            #pragma unroll
            for (int it = 0; it < 4; it++) {
                int idx = it * 256 + tid;
                int kk = idx >> 5;              // 0..31
                int n4 = (idx & 31) * 4;        // 0..124
                float4 v = *(const float4*)(B + (long)(k0 + kk) * N + bn + n4);
                uint4 u = make_uint4(f2tf(v.x), f2tf(v.y), f2tf(v.z), f2tf(v.w));
                *(uint4*)&Bs[kk * BSTRIDE + n4] = u;
            }
        }
        __syncthreads();

        #pragma unroll
        for (int ks = 0; ks < 4; ks++) {
            const int kk = ks * 8;
            uint32_t a[4][4], b[4][2];
            #pragma unroll
            for (int mf = 0; mf < 4; mf++) {
                int m0 = wm*64 + mf*16 + g;
                a[mf][0] = As[(m0    ) * ASTRIDE + kk + t    ];
                a[mf][1] = As[(m0 + 8) * ASTRIDE + kk + t    ];
                a[mf][2] = As[(m0    ) * ASTRIDE + kk + t + 4];
                a[mf][3] = As[(m0 + 8) * ASTRIDE + kk + t + 4];
            }
            #pragma unroll
            for (int nf = 0; nf < 4; nf++) {
                int n0 = wn*32 + nf*8 + g;
                if (TB) {
                    b[nf][0] = Bs[n0 * ASTRIDE + kk + t    ];
                    b[nf][1] = Bs[n0 * ASTRIDE + kk + t + 4];
                } else {
                    b[nf][0] = Bs[(kk + t    ) * BSTRIDE + n0];
                    b[nf][1] = Bs[(kk + t + 4) * BSTRIDE + n0];
                }
            }
            #pragma unroll
            for (int mf = 0; mf < 4; mf++)
                #pragma unroll
                for (int nf = 0; nf < 4; nf++)
                    mma_tf32(acc[mf][nf], a[mf], b[nf]);
        }
        __syncthreads();
    }

    // ---------------- epilogue ----------------
    #pragma unroll
    for (int mf = 0; mf < 4; mf++) {
        long r0 = bm + wm*64 + mf*16 + g;
        long r1 = r0 + 8;
        float g0 = 0.f, g1f = 0.f;
        if (EPI == EPI_GATEADD) { g0 = gate[r0]; g1f = gate[r1]; }
        #pragma unroll
        for (int nf = 0; nf < 4; nf++) {
            long c0 = bn + wn*32 + nf*8 + t*2;
            #pragma unroll
            for (int half = 0; half < 2; half++) {
                long row = half ? r1 : r0;
                float grow = half ? g1f : g0;
                float v0 = acc[mf][nf][half*2 + 0];
                float v1 = acc[mf][nf][half*2 + 1];
                float o0, o1;
                if (EPI == EPI_NONE) {
                    o0 = v0; o1 = v1;
                } else if (EPI == EPI_ELU1) {
                    o0 = (v0 > 0.f) ? (v0 + 1.f) : expf(v0);
                    o1 = (v1 > 0.f) ? (v1 + 1.f) : expf(v1);
                } else if (EPI == EPI_GATEADD) {
                    o0 = add[row * (long)N + c0    ] + grow * v0;
                    o1 = add[row * (long)N + c0 + 1] + grow * v1;
                } else if (EPI == EPI_ADD) {
                    o0 = v0 + add[row * (long)N + c0    ];
                    o1 = v1 + add[row * (long)N + c0 + 1];
                } else if (EPI == EPI_BIAS_GELU) {
                    float t0 = v0 + bias[c0], t1 = v1 + bias[c0 + 1];
                    o0 = 0.5f * t0 * (1.f + erff(t0 * 0.70710678118654752f));
                    o1 = 0.5f * t1 * (1.f + erff(t1 * 0.70710678118654752f));
                } else { // EPI_BIAS_ADD
                    o0 = v0 + bias[c0    ] + add[row * (long)N + c0    ];
                    o1 = v1 + bias[c0 + 1] + add[row * (long)N + c0 + 1];
                }
                float2 ov = make_float2(o0, o1);
                *(float2*)&C[row * (long)N + c0] = ov;
            }
        }
    }
}

// ---------------- row dot + sigmoid (read/write gates) ----------------
__global__ void rowgate_kernel(const float* __restrict__ X, long batchStride, int rowsPerBatch,
                               const float* __restrict__ W, const float* __restrict__ bsc,
                               float* __restrict__ out)
{
    int row = blockIdx.x;
    int b = row / rowsPerBatch;
    int t = row - b * rowsPerBatch;
    const float4* xr = (const float4*)(X + (long)b * batchStride + (long)t * DM);
    const float4* w4 = (const float4*)W;
    int tid = threadIdx.x;
    float4 a = xr[tid], w = w4[tid];
    float s = a.x*w.x + a.y*w.y + a.z*w.z + a.w*w.w;
    __shared__ float red[256];
    red[tid] = s; __syncthreads();
    for (int o = 128; o > 0; o >>= 1) { if (tid < o) red[tid] += red[tid + o]; __syncthreads(); }
    if (tid == 0) out[row] = 1.f / (1.f + expf(-(red[0] + bsc[0])));
}

// ---------------- softmax over 768 (with 1/sqrt(DC) scale) ----------------
__global__ void softmax768_kernel(float* __restrict__ s)
{
    long row = blockIdx.x;
    float* p = s + row * (long)MCACHE;
    int tid = threadIdx.x;
    __shared__ float red[256];
    float v0 = p[tid]       * SCALE_DC;
    float v1 = p[tid + 256] * SCALE_DC;
    float v2 = p[tid + 512] * SCALE_DC;
    float m = fmaxf(v0, fmaxf(v1, v2));
    red[tid] = m; __syncthreads();
    for (int o = 128; o > 0; o >>= 1) { if (tid < o) red[tid] = fmaxf(red[tid], red[tid+o]); __syncthreads(); }
    m = red[0]; __syncthreads();
    v0 = expf(v0 - m); v1 = expf(v1 - m); v2 = expf(v2 - m);
    red[tid] = v0 + v1 + v2; __syncthreads();
    for (int o = 128; o > 0; o >>= 1) { if (tid < o) red[tid] += red[tid+o]; __syncthreads(); }
    float inv = 1.f / red[0];
    p[tid] = v0 * inv; p[tid + 256] = v1 * inv; p[tid + 512] = v2 * inv;
}

// ---------------- linear attention: kv = pk^T v, ksum = sum pk (per b,h) ----------------
__global__ void kv_kernel(const float* __restrict__ pk, const float* __restrict__ v,
                          float* __restrict__ kvout, float* __restrict__ ksout)
{
    int bh = blockIdx.x;
    int b = bh / HH, h = bh % HH;
    const long baseoff = ((long)b * SS) * DM + (long)h * HDIM;
    __shared__ float pks[32][64];
    __shared__ float vs[32][64];
    int tid = threadIdx.x;
    int d0 = (tid >> 4) * 4;
    int e0 = (tid & 15) * 4;
    float acc[4][4];
    #pragma unroll
    for (int i=0;i<4;i++) { acc[i][0]=0;acc[i][1]=0;acc[i][2]=0;acc[i][3]=0; }
    float ks[4] = {0,0,0,0};
    int f0 = tid * 2;

    for (int s0 = 0; s0 < SS; s0 += 32) {
        #pragma unroll
        for (int i = 0; i < 2; i++) {
            int f = f0 + i;
            int r = f >> 4;
            int c = (f & 15) * 4;
            long gg = baseoff + (long)(s0 + r) * DM + c;
            *(float4*)&pks[r][c] = *(const float4*)(pk + gg);
            *(float4*)&vs[r][c]  = *(const float4*)(v  + gg);
        }
        __syncthreads();
        #pragma unroll 8
        for (int s = 0; s < 32; s++) {
            float4 pv = *(const float4*)&pks[s][d0];
            float4 vv = *(const float4*)&vs[s][e0];
            float pa[4] = {pv.x, pv.y, pv.z, pv.w};
            float va[4] = {vv.x, vv.y, vv.z, vv.w};
            #pragma unroll
            for (int i = 0; i < 4; i++)
                #pragma unroll
                for (int j = 0; j < 4; j++)
                    acc[i][j] = fmaf(pa[i], va[j], acc[i][j]);
            if (e0 == 0) {
                #pragma unroll
                for (int i = 0; i < 4; i++) ks[i] += pa[i];
            }
        }
        __syncthreads();
    }

    float* kvb = kvout + (long)bh * HDIM * HDIM;
    #pragma unroll
    for (int i = 0; i < 4; i++)
        #pragma unroll
        for (int j = 0; j < 4; j++)
            kvb[(d0 + i) * 64 + e0 + j] = acc[i][j];
    if (e0 == 0) {
        float* ksb = ksout + (long)bh * HDIM;
        #pragma unroll
        for (int i = 0; i < 4; i++) ksb[d0 + i] = ks[i];
    }
}

// ---------------- linear attention: attn = (pq @ kv) / (pq·ksum + eps) ----------------
__global__ void numden_kernel(const float* __restrict__ pq, const float* __restrict__ kv,
                              const float* __restrict__ ksum, float* __restrict__ attn)
{
    int bh = blockIdx.x;
    int b = bh / HH, h = bh % HH;
    __shared__ float kvs[64*64];
    __shared__ float kss[64];
    int tid = threadIdx.x;
    {
        const float4* kvb = (const float4*)(kv + (long)bh * 4096);
        for (int i = tid; i < 1024; i += 256) ((float4*)kvs)[i] = kvb[i];
        if (tid < 16) ((float4*)kss)[tid] = ((const float4*)(ksum + (long)bh * 64))[tid];
    }
    __syncthreads();

    int srow = blockIdx.y * 128 + (tid >> 1);
    int e0 = (tid & 1) * 32;
    const float* qr = pq + ((long)b * SS + srow) * DM + (long)h * HDIM;
    float num[32];
    #pragma unroll
    for (int e = 0; e < 32; e++) num[e] = 0.f;
    float den = 0.f;

    #pragma unroll
    for (int d4 = 0; d4 < 16; d4++) {
        float4 qv = *(const float4*)(qr + d4 * 4);
        float qa[4] = {qv.x, qv.y, qv.z, qv.w};
        #pragma unroll
        for (int dd = 0; dd < 4; dd++) {
            int d = d4 * 4 + dd;
            den = fmaf(qa[dd], kss[d], den);
            const float* kr = &kvs[d * 64 + e0];
            #pragma unroll
            for (int e = 0; e < 32; e++) num[e] = fmaf(qa[dd], kr[e], num[e]);
        }
    }
    float inv = 1.f / (den + 1e-6f);
    float* o = attn + ((long)b * SS + srow) * DM + (long)h * HDIM + e0;
    #pragma unroll
    for (int e = 0; e < 32; e++) o[e] = num[e] * inv;
}

// ---------------- fused double LayerNorm: x1 = LN(z;n1), h = LN(x1;ln0) ----------------
__global__ void double_ln_kernel(const float* __restrict__ z,
    const float* __restrict__ g1, const float* __restrict__ b1,
    const float* __restrict__ g0, const float* __restrict__ b0,
    float* __restrict__ x1, float* __restrict__ h)
{
    long row = blockIdx.x;
    int tid = threadIdx.x;
    __shared__ float red[256];
    float4 v = ((const float4*)(z + row * (long)DM))[tid];

    float s = v.x + v.y + v.z + v.w;
    red[tid] = s; __syncthreads();
    for (int o = 128; o > 0; o >>= 1) { if (tid < o) red[tid] += red[tid+o]; __syncthreads(); }
    float m = red[0] * (1.f/1024.f); __syncthreads();
    float dx = v.x-m, dy = v.y-m, dz = v.z-m, dw = v.w-m;
    red[tid] = dx*dx + dy*dy + dz*dz + dw*dw; __syncthreads();
    for (int o = 128; o > 0; o >>= 1) { if (tid < o) red[tid] += red[tid+o]; __syncthreads(); }
    float rstd = rsqrtf(red[0] * (1.f/1024.f) + 1e-5f); __syncthreads();

    float4 g = ((const float4*)g1)[tid];
    float4 bb = ((const float4*)b1)[tid];
    float4 o1;
    o1.x = g.x * dx * rstd + bb.x;
    o1.y = g.y * dy * rstd + bb.y;
    o1.z = g.z * dz * rstd + bb.z;
    o1.w = g.w * dw * rstd + bb.w;
    ((float4*)(x1 + row * (long)DM))[tid] = o1;

    float s2 = o1.x + o1.y + o1.z + o1.w;
    red[tid] = s2; __syncthreads();
    for (int o = 128; o > 0; o >>= 1) { if (tid < o) red[tid] += red[tid+o]; __syncthreads(); }
    float m2 = red[0] * (1.f/1024.f); __syncthreads();
    float ex = o1.x-m2, ey = o1.y-m2, ez = o1.z-m2, ew = o1.w-m2;
    red[tid] = ex*ex + ey*ey + ez*ez + ew*ew; __syncthreads();
    for (int o = 128; o > 0; o >>= 1) { if (tid < o) red[tid] += red[tid+o]; __syncthreads(); }
    float rstd2 = rsqrtf(red[0] * (1.f/1024.f) + 1e-5f); __syncthreads();

    float4 gg = ((const float4*)g0)[tid];
    float4 b2v = ((const float4*)b0)[tid];
    float4 o2;
    o2.x = gg.x * ex * rstd2 + b2v.x;
    o2.y = gg.y * ey * rstd2 + b2v.y;
    o2.z = gg.z * ez * rstd2 + b2v.z;
    o2.w = gg.w * ew * rstd2 + b2v.w;
    ((float4*)(h + row * (long)DM))[tid] = o2;
}

// ---------------- single LayerNorm (final y) ----------------
__global__ void final_ln_kernel(const float* __restrict__ z,
    const float* __restrict__ g, const float* __restrict__ b,
    float* __restrict__ y)
{
    long row = blockIdx.x;
    int tid = threadIdx.x;
    __shared__ float red[256];
    float4 v = ((const float4*)(z + row * (long)DM))[tid];
    red[tid] = v.x + v.y + v.z + v.w; __syncthreads();
    for (int o = 128; o > 0; o >>= 1) { if (tid < o) red[tid] += red[tid+o]; __syncthreads(); }
    float m = red[0] * (1.f/1024.f); __syncthreads();
    float dx = v.x-m, dy = v.y-m, dz = v.z-m, dw = v.w-m;
    red[tid] = dx*dx + dy*dy + dz*dz + dw*dw; __syncthreads();
    for (int o = 128; o > 0; o >>= 1) { if (tid < o) red[tid] += red[tid+o]; __syncthreads(); }
    float rstd = rsqrtf(red[0] * (1.f/1024.f) + 1e-5f);

    float4 gv = ((const float4*)g)[tid];
    float4 bv = ((const float4*)b)[tid];
    float4 o;
    o.x = gv.x * dx * rstd + bv.x;
    o.y = gv.y * dy * rstd + bv.y;
    o.z = gv.z * dz * rstd + bv.z;
    o.w = gv.w * dw * rstd + bv.w;
    ((float4*)(y + row * (long)DM))[tid] = o;
}

// ---------------- write path: slot logits + softmax + gate -> p ----------------
__global__ void slot_kernel(const float* __restrict__ wproj, const float* __restrict__ cache,
                            const float* __restrict__ wgate, float* __restrict__ p)
{
    int blk = blockIdx.x;
    int b = blk >> 8;
    int t = blk & 255;
    int k = threadIdx.x;
    const float4* wp = (const float4*)(wproj + ((long)b * TT + t) * DCC);
    const float4* lr = (const float4*)(cache + ((long)b * MCACHE + LAYER_OFF + k) * DCC);
    float dot = 0.f;
    #pragma unroll 8
    for (int c = 0; c < 128; c++) {
        float4 a = wp[c], w = lr[c];
        dot += a.x*w.x + a.y*w.y + a.z*w.z + a.w*w.w;
    }
    float logit = dot * SCALE_DC;
    __shared__ float red[64];
    red[k] = logit; __syncthreads();
    for (int o = 32; o > 0; o >>= 1) { if (k < o) red[k] = fmaxf(red[k], red[k+o]); __syncthreads(); }
    float m = red[0]; __syncthreads();
    float e = expf(logit - m);
    red[k] = e; __syncthreads();
    for (int o = 32; o > 0; o >>= 1) { if (k < o) red[k] += red[k+o]; __syncthreads(); }
    float val = e / red[0] * wgate[b * TT + t];
    p[((long)b * TT + t) * KSLOT + k] = val;
}

// ---------------- write path: out_cache[slice] += p^T vals ----------------
__global__ void update_kernel(const float* __restrict__ p, const float* __restrict__ vals,
                              float* __restrict__ out_cache)
{
    int blk = blockIdx.x;
    int b = blk >> 6;
    int k = blk & 63;
    int c0 = threadIdx.x * 2;
    float a0 = 0.f, a1 = 0.f;
    for (int t = 0; t < TT; t++) {
        float pv = p[((long)b * TT + t) * KSLOT + k];
        const float* vr = vals + ((long)b * TT + t) * DCC;
        a0 = fmaf(pv, vr[c0],     a0);
        a1 = fmaf(pv, vr[c0 + 1], a1);
    }
    float* oc = out_cache + ((long)b * MCACHE + LAYER_OFF + k) * DCC;
    oc[c0]     += a0;
    oc[c0 + 1] += a1;
}

// ---------------- launch ----------------
extern "C" void kernel_launch(void* const* d_in, const int* in_sizes, int n_in,
                              void* d_out_, int out_size)
{
    const float* x     = (const float*)d_in[0];
    const float* cache = (const float*)d_in[1];
    const float* Wq_r  = (const float*)d_in[2];
    const float* Wo_r  = (const float*)d_in[3];
    const float* Wg_r  = (const float*)d_in[4];
    const float* bg_r  = (const float*)d_in[5];
    const float* Wq    = (const float*)d_in[6];
    const float* Wk    = (const float*)d_in[7];
    const float* Wv    = (const float*)d_in[8];
    const float* Wo    = (const float*)d_in[9];
    const float* ln0g  = (const float*)d_in[10];
    const float* ln0b  = (const float*)d_in[11];
    const float* W1    = (const float*)d_in[12];
    const float* b1    = (const float*)d_in[13];
    const float* W2    = (const float*)d_in[14];
    const float* b2    = (const float*)d_in[15];
    const float* n1g   = (const float*)d_in[16];
    const float* n1b   = (const float*)d_in[17];
    const float* n2g   = (const float*)d_in[18];
    const float* n2b   = (const float*)d_in[19];
    /* d_in[20] = Ws : unused (write_scores dead in reference) */
    const float* Wgw   = (const float*)d_in[21];
    const float* bgw   = (const float*)d_in[22];
    const float* Wslot = (const float*)d_in[23];
    const float* Wvw   = (const float*)d_in[24];

    float* out       = (float*)d_out_;
    float* y_out     = out;
    float* cache_out = out + (size_t)NROWS * DM;

    float *p_qr, *p_scores, *p_ctx, *p_gate, *p_fused, *p_pq, *p_pk, *p_v;
    float *p_kv, *p_ksum, *p_attn, *p_z, *p_x1, *p_h, *p_t1, *p_z2;
    float *p_wproj, *p_vals, *p_wgate, *p_p;
    cudaGetSymbolAddress((void**)&p_qr,     g_qr);
    cudaGetSymbolAddress((void**)&p_scores, g_scores);
    cudaGetSymbolAddress((void**)&p_ctx,    g_ctx);
    cudaGetSymbolAddress((void**)&p_gate,   g_gate);
    cudaGetSymbolAddress((void**)&p_fused,  g_fused);
    cudaGetSymbolAddress((void**)&p_pq,     g_pq);
    cudaGetSymbolAddress((void**)&p_pk,     g_pk);
    cudaGetSymbolAddress((void**)&p_v,      g_v);
    cudaGetSymbolAddress((void**)&p_kv,     g_kv);
    cudaGetSymbolAddress((void**)&p_ksum,   g_ksum);
    cudaGetSymbolAddress((void**)&p_attn,   g_attn);
    cudaGetSymbolAddress((void**)&p_z,      g_z);
    cudaGetSymbolAddress((void**)&p_x1,     g_x1);
    cudaGetSymbolAddress((void**)&p_h,      g_h);
    cudaGetSymbolAddress((void**)&p_t1,     g_t1);
    cudaGetSymbolAddress((void**)&p_z2,     g_z2);
    cudaGetSymbolAddress((void**)&p_wproj,  g_wproj);
    cudaGetSymbolAddress((void**)&p_vals,   g_vals);
    cudaGetSymbolAddress((void**)&p_wgate,  g_wgate);
    cudaGetSymbolAddress((void**)&p_p,      g_p);

    const long ZL = 0;

    // read gate: sigmoid(x @ Wg_r + bg_r)
    rowgate_kernel<<<NROWS, 256>>>(x, ZL, NROWS, Wg_r, bg_r, p_gate);

    // q_r = x @ Wq_r          [16384 x 512]
    tgemm_kernel<EPI_NONE,false><<<dim3(DCC/BN, NROWS/BM, 1), 256>>>(
        x, Wq_r, p_qr, NROWS, DCC, DM, ZL, ZL, ZL, nullptr, nullptr, ZL, nullptr);

    // scores = q_r @ cache^T  (batched NT)  [4 x 4096 x 768]
    tgemm_kernel<EPI_NONE,true><<<dim3(MCACHE/BN, SS/BM, BB), 256>>>(
        p_qr, cache, p_scores, SS, MCACHE, DCC,
        (long)SS*DCC, (long)MCACHE*DCC, (long)SS*MCACHE, nullptr, nullptr, ZL, nullptr);

    // softmax(scores / sqrt(DC))
    softmax768_kernel<<<NROWS, 256>>>(p_scores);

    // ctx = attn @ cache      (batched NN)  [4 x 4096 x 512]
    tgemm_kernel<EPI_NONE,false><<<dim3(DCC/BN, SS/BM, BB), 256>>>(
        p_scores, cache, p_ctx, SS, DCC, MCACHE,
        (long)SS*MCACHE, (long)MCACHE*DCC, (long)SS*DCC, nullptr, nullptr, ZL, nullptr);

    // fused = x + gate * (ctx @ Wo_r)
    tgemm_kernel<EPI_GATEADD,false><<<dim3(DM/BN, NROWS/BM, 1), 256>>>(
        p_ctx, Wo_r, p_fused, NROWS, DM, DCC, ZL, ZL, ZL, nullptr, x, ZL, p_gate);

    // pq = elu(fused @ Wq)+1, pk = elu(fused @ Wk)+1, v = fused @ Wv
    tgemm_kernel<EPI_ELU1,false><<<dim3(DM/BN, NROWS/BM, 1), 256>>>(
        p_fused, Wq, p_pq, NROWS, DM, DM, ZL, ZL, ZL, nullptr, nullptr, ZL, nullptr);
    tgemm_kernel<EPI_ELU1,false><<<dim3(DM/BN, NROWS/BM, 1), 256>>>(
        p_fused, Wk, p_pk, NROWS, DM, DM, ZL, ZL, ZL, nullptr, nullptr, ZL, nullptr);
    tgemm_kernel<EPI_NONE,false><<<dim3(DM/BN, NROWS/BM, 1), 256>>>(
        p_fused, Wv, p_v, NROWS, DM, DM, ZL, ZL, ZL, nullptr, nullptr, ZL, nullptr);

    // linear attention
    kv_kernel<<<BB*HH, 256>>>(p_pk, p_v, p_kv, p_ksum);
    numden_kernel<<<dim3(BB*HH, SS/128), 256>>>(p_pq, p_kv, p_ksum, p_attn);

    // z = fused + attn @ Wo
    tgemm_kernel<EPI_ADD,false><<<dim3(DM/BN, NROWS/BM, 1), 256>>>(
        p_attn, Wo, p_z, NROWS, DM, DM, ZL, ZL, ZL, nullptr, p_fused, ZL, nullptr);

    // x1 = LN(z; n1), h = LN(x1; ln0)
    double_ln_kernel<<<NROWS, 256>>>(p_z, n1g, n1b, ln0g, ln0b, p_x1, p_h);

    // t1 = gelu(h @ W1 + b1)
    tgemm_kernel<EPI_BIAS_GELU,false><<<dim3(DFF/BN, NROWS/BM, 1), 256>>>(
        p_h, W1, p_t1, NROWS, DFF, DM, ZL, ZL, ZL, b1, nullptr, ZL, nullptr);

    // z2 = x1 + t1 @ W2 + b2
    tgemm_kernel<EPI_BIAS_ADD,false><<<dim3(DM/BN, NROWS/BM, 1), 256>>>(
        p_t1, W2, p_z2, NROWS, DM, DFF, ZL, ZL, ZL, b2, p_x1, ZL, nullptr);

    // y = LN(z2; n2)  -> straight into d_out
    final_ln_kernel<<<NROWS, 256>>>(p_z2, n2g, n2b, y_out);

    // ---- write path on wc = y[:, :256, :] ----
    tgemm_kernel<EPI_NONE,false><<<dim3(DCC/BN, TT/BM, BB), 256>>>(
        y_out, Wslot, p_wproj, TT, DCC, DM,
        (long)SS*DM, ZL, (long)TT*DCC, nullptr, nullptr, ZL, nullptr);
    tgemm_kernel<EPI_NONE,false><<<dim3(DCC/BN, TT/BM, BB), 256>>>(
        y_out, Wvw, p_vals, TT, DCC, DM,
        (long)SS*DM, ZL, (long)TT*DCC, nullptr, nullptr, ZL, nullptr);

    // write gate
    rowgate_kernel<<<BB*TT, 256>>>(y_out, (long)SS*DM, TT, Wgw, bgw, p_wgate);

    // slot probs * gate
    slot_kernel<<<BB*TT, 64>>>(p_wproj, cache, p_wgate, p_p);

    // new_cache = cache; new_cache[:, layer slice] += p^T vals
    cudaMemcpyAsync(cache_out, cache, (size_t)BB*MCACHE*DCC*sizeof(float),
                    cudaMemcpyDeviceToDevice, 0);
    update_kernel<<<BB*KSLOT, 256>>>(p_p, p_vals, cache_out);
}

// round 13
// speedup vs baseline: 3.3573x; 1.1871x over previous
#include <cuda_runtime.h>
#include <math.h>
#include <stdint.h>

// ---------------- problem constants ----------------
#define BB      4
#define SS      4096
#define DM      1024
#define HH      16
#define HDIM    64
#define DCC     512
#define KSLOT   64
#define MCACHE  768          // L*K = 12*64
#define TT      256          // min(S, 4K)
#define DFF     4096
#define LAYER_OFF 192        // LAYER*K = 3*64
#define NROWS   (BB*SS)      // 16384
#define SCALE_DC 0.044194173824159216f   // 1/sqrt(512)
#define KVCH    8            // kv split chunks

// ---------------- scratch (static device memory; allocation-free) ----------------
__device__ float g_qr    [(size_t)NROWS*DCC];
__device__ float g_scores[(size_t)NROWS*MCACHE];
__device__ float g_ctx   [(size_t)NROWS*DCC];
__device__ float g_gate  [(size_t)NROWS];
__device__ float g_fused [(size_t)NROWS*DM];
__device__ float g_pq    [(size_t)NROWS*DM];
__device__ float g_pk    [(size_t)NROWS*DM];
__device__ float g_v     [(size_t)NROWS*DM];
__device__ float g_kv    [(size_t)BB*HH*HDIM*HDIM];
__device__ float g_ksum  [(size_t)BB*HH*HDIM];
__device__ float g_kvpart[(size_t)KVCH*BB*HH*HDIM*HDIM];
__device__ float g_kspart[(size_t)KVCH*BB*HH*HDIM];
__device__ float g_attn  [(size_t)NROWS*DM];
__device__ float g_z     [(size_t)NROWS*DM];
__device__ float g_x1    [(size_t)NROWS*DM];
__device__ float g_h     [(size_t)NROWS*DM];
__device__ float g_t1    [(size_t)NROWS*DFF];
__device__ float g_z2    [(size_t)NROWS*DM];
__device__ float g_wproj [(size_t)BB*TT*DCC];
__device__ float g_vals  [(size_t)BB*TT*DCC];
__device__ float g_wgate [(size_t)BB*TT];
__device__ float g_p     [(size_t)BB*TT*KSLOT];

// ---------------- TF32 tensor-core GEMM: 128x128x32, 8 warps, cp.async 2-stage ----------------
#define BM 128
#define BN 128
#define BKK 32
#define ASTRIDE 40    // BKK + 8  -> conflict-free STS.128 and fragment LDS
#define BSTRIDE 136   // BN  + 8  -> conflict-free STS.128 and fragment LDS
#define ASIZE (BM*ASTRIDE)                 // floats per A stage = 5120

enum { EPI_NONE=0, EPI_ELU1=1, EPI_GATEADD=2, EPI_ADD=3, EPI_BIAS_GELU=4, EPI_BIAS_ADD=5 };

__device__ __forceinline__ uint32_t f2tf(float f) {
    uint32_t u;
    asm("cvt.rna.tf32.f32 %0, %1;" : "=r"(u) : "f"(f));
    return u;
}

__device__ __forceinline__ void mma_tf32(float* c, const uint32_t* a, const uint32_t* b) {
    asm("mma.sync.aligned.m16n8k8.row.col.f32.tf32.tf32.f32 "
        "{%0,%1,%2,%3}, {%4,%5,%6,%7}, {%8,%9}, {%0,%1,%2,%3};"
        : "+f"(c[0]), "+f"(c[1]), "+f"(c[2]), "+f"(c[3])
        : "r"(a[0]), "r"(a[1]), "r"(a[2]), "r"(a[3]), "r"(b[0]), "r"(b[1]));
}

__device__ __forceinline__ void cp_async16(float* smem_dst, const float* gsrc) {
    uint32_t s = (uint32_t)__cvta_generic_to_shared(smem_dst);
    asm volatile("cp.async.cg.shared.global [%0], [%1], 16;" :: "r"(s), "l"(gsrc));
}

template<int EPI, bool TB>
__global__ __launch_bounds__(256, 2) void tgemm_kernel(
    const float* __restrict__ A, const float* __restrict__ B, float* __restrict__ C,
    int M, int N, int K,
    long sA, long sB, long sC,
    const float* __restrict__ bias,
    const float* __restrict__ add, long sAdd,
    const float* __restrict__ gate)
{
    extern __shared__ float smem[];
    const int BSIZE = TB ? (BN * ASTRIDE) : (BKK * BSTRIDE);
    float* As = smem;                       // [2][ASIZE]
    float* Bs = smem + 2 * ASIZE;           // [2][BSIZE]

    const int bz = blockIdx.z;
    A += (long)bz * sA;
    B += (long)bz * sB;
    C += (long)bz * sC;
    if (EPI==EPI_GATEADD || EPI==EPI_ADD || EPI==EPI_BIAS_ADD) add += (long)bz * sAdd;

    const long bm = (long)blockIdx.y * BM;
    const long bn = (long)blockIdx.x * BN;
    const int tid  = threadIdx.x;
    const int lane = tid & 31;
    const int warp = tid >> 5;
    const int wm = warp & 1;        // 2 warps along M -> 128
    const int wn = warp >> 1;       // 4 warps along N -> 128
    const int g  = lane >> 2;       // 0..7
    const int t  = lane & 3;        // 0..3

    // per-thread load coordinates (same each tile)
    const int arow[4] = { (0*256+tid)>>3, (1*256+tid)>>3, (2*256+tid)>>3, (3*256+tid)>>3 };
    const int ac4 = (tid & 7) * 4;

    float acc[4][4][4];
    #pragma unroll
    for (int i = 0; i < 4; i++)
        #pragma unroll
        for (int j = 0; j < 4; j++) {
            acc[i][j][0]=0.f; acc[i][j][1]=0.f; acc[i][j][2]=0.f; acc[i][j][3]=0.f;
        }

    const int KT = K / BKK;

    // ---- tile loader (cp.async, 16B granules) ----
    auto load_tiles = [&](int kt, int stage) {
        const int k0 = kt * BKK;
        float* as = As + stage * ASIZE;
        float* bs = Bs + stage * BSIZE;
        #pragma unroll
        for (int it = 0; it < 4; it++) {
            int row = arow[it];
            cp_async16(as + row * ASTRIDE + ac4, A + (bm + row) * (long)K + k0 + ac4);
        }
        if (TB) {
            #pragma unroll
            for (int it = 0; it < 4; it++) {
                int row = arow[it];
                cp_async16(bs + row * ASTRIDE + ac4, B + (bn + row) * (long)K + k0 + ac4);
            }
        } else {
            #pragma unroll
            for (int it = 0; it < 4; it++) {
                int idx = it * 256 + tid;
                int kk = idx >> 5;
                int n4 = (idx & 31) * 4;
                cp_async16(bs + kk * BSTRIDE + n4, B + (long)(k0 + kk) * N + bn + n4);
            }
        }
    };

    // prologue: stage 0
    load_tiles(0, 0);
    asm volatile("cp.async.commit_group;");

    for (int kt = 0; kt < KT; kt++) {
        const int buf = kt & 1;
        if (kt + 1 < KT) {
            load_tiles(kt + 1, buf ^ 1);
            asm volatile("cp.async.commit_group;");
            asm volatile("cp.async.wait_group 1;");
        } else {
            asm volatile("cp.async.wait_group 0;");
        }
        __syncthreads();

        const float* as = As + buf * ASIZE;
        const float* bs = Bs + buf * BSIZE;

        #pragma unroll
        for (int ks = 0; ks < 4; ks++) {
            const int kk = ks * 8;
            uint32_t a[4][4], b[4][2];
            #pragma unroll
            for (int mf = 0; mf < 4; mf++) {
                int m0 = wm*64 + mf*16 + g;
                a[mf][0] = f2tf(as[(m0    ) * ASTRIDE + kk + t    ]);
                a[mf][1] = f2tf(as[(m0 + 8) * ASTRIDE + kk + t    ]);
                a[mf][2] = f2tf(as[(m0    ) * ASTRIDE + kk + t + 4]);
                a[mf][3] = f2tf(as[(m0 + 8) * ASTRIDE + kk + t + 4]);
            }
            #pragma unroll
            for (int nf = 0; nf < 4; nf++) {
                int n0 = wn*32 + nf*8 + g;
                if (TB) {
                    b[nf][0] = f2tf(bs[n0 * ASTRIDE + kk + t    ]);
                    b[nf][1] = f2tf(bs[n0 * ASTRIDE + kk + t + 4]);
                } else {
                    b[nf][0] = f2tf(bs[(kk + t    ) * BSTRIDE + n0]);
                    b[nf][1] = f2tf(bs[(kk + t + 4) * BSTRIDE + n0]);
                }
            }
            #pragma unroll
            for (int mf = 0; mf < 4; mf++)
                #pragma unroll
                for (int nf = 0; nf < 4; nf++)
                    mma_tf32(acc[mf][nf], a[mf], b[nf]);
        }
        __syncthreads();
    }

    // ---------------- epilogue ----------------
    #pragma unroll
    for (int mf = 0; mf < 4; mf++) {
        long r0 = bm + wm*64 + mf*16 + g;
        long r1 = r0 + 8;
        float g0 = 0.f, g1f = 0.f;
        if (EPI == EPI_GATEADD) { g0 = gate[r0]; g1f = gate[r1]; }
        #pragma unroll
        for (int nf = 0; nf < 4; nf++) {
            long c0 = bn + wn*32 + nf*8 + t*2;
            #pragma unroll
            for (int half = 0; half < 2; half++) {
                long row = half ? r1 : r0;
                float grow = half ? g1f : g0;
                float v0 = acc[mf][nf][half*2 + 0];
                float v1 = acc[mf][nf][half*2 + 1];
                float o0, o1;
                if (EPI == EPI_NONE) {
                    o0 = v0; o1 = v1;
                } else if (EPI == EPI_ELU1) {
                    o0 = (v0 > 0.f) ? (v0 + 1.f) : expf(v0);
                    o1 = (v1 > 0.f) ? (v1 + 1.f) : expf(v1);
                } else if (EPI == EPI_GATEADD) {
                    o0 = add[row * (long)N + c0    ] + grow * v0;
                    o1 = add[row * (long)N + c0 + 1] + grow * v1;
                } else if (EPI == EPI_ADD) {
                    o0 = v0 + add[row * (long)N + c0    ];
                    o1 = v1 + add[row * (long)N + c0 + 1];
                } else if (EPI == EPI_BIAS_GELU) {
                    float t0 = v0 + bias[c0], t1 = v1 + bias[c0 + 1];
                    o0 = 0.5f * t0 * (1.f + erff(t0 * 0.70710678118654752f));
                    o1 = 0.5f * t1 * (1.f + erff(t1 * 0.70710678118654752f));
                } else { // EPI_BIAS_ADD
                    o0 = v0 + bias[c0    ] + add[row * (long)N + c0    ];
                    o1 = v1 + bias[c0 + 1] + add[row * (long)N + c0 + 1];
                }
                float2 ov = make_float2(o0, o1);
                *(float2*)&C[row * (long)N + c0] = ov;
            }
        }
    }
}

// ---------------- row dot + sigmoid (read/write gates) ----------------
__global__ void rowgate_kernel(const float* __restrict__ X, long batchStride, int rowsPerBatch,
                               const float* __restrict__ W, const float* __restrict__ bsc,
                               float* __restrict__ out)
{
    int row = blockIdx.x;
    int b = row / rowsPerBatch;
    int t = row - b * rowsPerBatch;
    const float4* xr = (const float4*)(X + (long)b * batchStride + (long)t * DM);
    const float4* w4 = (const float4*)W;
    int tid = threadIdx.x;
    float4 a = xr[tid], w = w4[tid];
    float s = a.x*w.x + a.y*w.y + a.z*w.z + a.w*w.w;
    __shared__ float red[256];
    red[tid] = s; __syncthreads();
    for (int o = 128; o > 0; o >>= 1) { if (tid < o) red[tid] += red[tid + o]; __syncthreads(); }
    if (tid == 0) out[row] = 1.f / (1.f + expf(-(red[0] + bsc[0])));
}

// ---------------- softmax over 768 (with 1/sqrt(DC) scale) ----------------
__global__ void softmax768_kernel(float* __restrict__ s)
{
    long row = blockIdx.x;
    float* p = s + row * (long)MCACHE;
    int tid = threadIdx.x;
    __shared__ float red[256];
    float v0 = p[tid]       * SCALE_DC;
    float v1 = p[tid + 256] * SCALE_DC;
    float v2 = p[tid + 512] * SCALE_DC;
    float m = fmaxf(v0, fmaxf(v1, v2));
    red[tid] = m; __syncthreads();
    for (int o = 128; o > 0; o >>= 1) { if (tid < o) red[tid] = fmaxf(red[tid], red[tid+o]); __syncthreads(); }
    m = red[0]; __syncthreads();
    v0 = expf(v0 - m); v1 = expf(v1 - m); v2 = expf(v2 - m);
    red[tid] = v0 + v1 + v2; __syncthreads();
    for (int o = 128; o > 0; o >>= 1) { if (tid < o) red[tid] += red[tid+o]; __syncthreads(); }
    float inv = 1.f / red[0];
    p[tid] = v0 * inv; p[tid + 256] = v1 * inv; p[tid + 512] = v2 * inv;
}

// ---------------- linear attention: partial kv over a seq chunk ----------------
__global__ void kvpart_kernel(const float* __restrict__ pk, const float* __restrict__ v,
                              float* __restrict__ kvpart, float* __restrict__ kspart)
{
    int bh = blockIdx.x;
    int ch = blockIdx.y;
    int b = bh / HH, h = bh % HH;
    const long baseoff = ((long)b * SS) * DM + (long)h * HDIM;
    const int s_begin = ch * (SS / KVCH);
    const int s_end   = s_begin + (SS / KVCH);
    __shared__ float pks[32][64];
    __shared__ float vs[32][64];
    int tid = threadIdx.x;
    int d0 = (tid >> 4) * 4;
    int e0 = (tid & 15) * 4;
    float acc[4][4];
    #pragma unroll
    for (int i=0;i<4;i++) { acc[i][0]=0;acc[i][1]=0;acc[i][2]=0;acc[i][3]=0; }
    float ks[4] = {0,0,0,0};
    int f0 = tid * 2;

    for (int s0 = s_begin; s0 < s_end; s0 += 32) {
        #pragma unroll
        for (int i = 0; i < 2; i++) {
            int f = f0 + i;
            int r = f >> 4;
            int c = (f & 15) * 4;
            long gg = baseoff + (long)(s0 + r) * DM + c;
            *(float4*)&pks[r][c] = *(const float4*)(pk + gg);
            *(float4*)&vs[r][c]  = *(const float4*)(v  + gg);
        }
        __syncthreads();
        #pragma unroll 8
        for (int s = 0; s < 32; s++) {
            float4 pv = *(const float4*)&pks[s][d0];
            float4 vv = *(const float4*)&vs[s][e0];
            float pa[4] = {pv.x, pv.y, pv.z, pv.w};
            float va[4] = {vv.x, vv.y, vv.z, vv.w};
            #pragma unroll
            for (int i = 0; i < 4; i++)
                #pragma unroll
                for (int j = 0; j < 4; j++)
                    acc[i][j] = fmaf(pa[i], va[j], acc[i][j]);
            if (e0 == 0) {
                #pragma unroll
                for (int i = 0; i < 4; i++) ks[i] += pa[i];
            }
        }
        __syncthreads();
    }

    float* kvb = kvpart + ((long)ch * BB * HH + bh) * HDIM * HDIM;
    #pragma unroll
    for (int i = 0; i < 4; i++)
        #pragma unroll
        for (int j = 0; j < 4; j++)
            kvb[(d0 + i) * 64 + e0 + j] = acc[i][j];
    if (e0 == 0) {
        float* ksb = kspart + ((long)ch * BB * HH + bh) * HDIM;
        #pragma unroll
        for (int i = 0; i < 4; i++) ksb[d0 + i] = ks[i];
    }
}

__global__ void kvreduce_kernel(const float* __restrict__ kvpart, const float* __restrict__ kspart,
                                float* __restrict__ kvout, float* __restrict__ ksout)
{
    int bh = blockIdx.x;
    int tid = threadIdx.x;
    for (int i = tid; i < HDIM*HDIM; i += 256) {
        float s = 0.f;
        #pragma unroll
        for (int ch = 0; ch < KVCH; ch++)
            s += kvpart[((long)ch * BB * HH + bh) * HDIM * HDIM + i];
        kvout[(long)bh * HDIM * HDIM + i] = s;
    }
    if (tid < HDIM) {
        float s = 0.f;
        #pragma unroll
        for (int ch = 0; ch < KVCH; ch++)
            s += kspart[((long)ch * BB * HH + bh) * HDIM + tid];
        ksout[(long)bh * HDIM + tid] = s;
    }
}

// ---------------- linear attention: attn = (pq @ kv) / (pq·ksum + eps) ----------------
__global__ void numden_kernel(const float* __restrict__ pq, const float* __restrict__ kv,
                              const float* __restrict__ ksum, float* __restrict__ attn)
{
    int bh = blockIdx.x;
    int b = bh / HH, h = bh % HH;
    __shared__ float kvs[64*64];
    __shared__ float kss[64];
    int tid = threadIdx.x;
    {
        const float4* kvb = (const float4*)(kv + (long)bh * 4096);
        for (int i = tid; i < 1024; i += 256) ((float4*)kvs)[i] = kvb[i];
        if (tid < 16) ((float4*)kss)[tid] = ((const float4*)(ksum + (long)bh * 64))[tid];
    }
    __syncthreads();

    int srow = blockIdx.y * 128 + (tid >> 1);
    int e0 = (tid & 1) * 32;
    const float* qr = pq + ((long)b * SS + srow) * DM + (long)h * HDIM;
    float num[32];
    #pragma unroll
    for (int e = 0; e < 32; e++) num[e] = 0.f;
    float den = 0.f;

    #pragma unroll
    for (int d4 = 0; d4 < 16; d4++) {
        float4 qv = *(const float4*)(qr + d4 * 4);
        float qa[4] = {qv.x, qv.y, qv.z, qv.w};
        #pragma unroll
        for (int dd = 0; dd < 4; dd++) {
            int d = d4 * 4 + dd;
            den = fmaf(qa[dd], kss[d], den);
            const float* kr = &kvs[d * 64 + e0];
            #pragma unroll
            for (int e = 0; e < 32; e++) num[e] = fmaf(qa[dd], kr[e], num[e]);
        }
    }
    float inv = 1.f / (den + 1e-6f);
    float* o = attn + ((long)b * SS + srow) * DM + (long)h * HDIM + e0;
    #pragma unroll
    for (int e = 0; e < 32; e++) o[e] = num[e] * inv;
}

// ---------------- fused double LayerNorm: x1 = LN(z;n1), h = LN(x1;ln0) ----------------
__global__ void double_ln_kernel(const float* __restrict__ z,
    const float* __restrict__ g1, const float* __restrict__ b1,
    const float* __restrict__ g0, const float* __restrict__ b0,
    float* __restrict__ x1, float* __restrict__ h)
{
    long row = blockIdx.x;
    int tid = threadIdx.x;
    __shared__ float red[256];
    float4 v = ((const float4*)(z + row * (long)DM))[tid];

    float s = v.x + v.y + v.z + v.w;
    red[tid] = s; __syncthreads();
    for (int o = 128; o > 0; o >>= 1) { if (tid < o) red[tid] += red[tid+o]; __syncthreads(); }
    float m = red[0] * (1.f/1024.f); __syncthreads();
    float dx = v.x-m, dy = v.y-m, dz = v.z-m, dw = v.w-m;
    red[tid] = dx*dx + dy*dy + dz*dz + dw*dw; __syncthreads();
    for (int o = 128; o > 0; o >>= 1) { if (tid < o) red[tid] += red[tid+o]; __syncthreads(); }
    float rstd = rsqrtf(red[0] * (1.f/1024.f) + 1e-5f); __syncthreads();

    float4 g = ((const float4*)g1)[tid];
    float4 bb = ((const float4*)b1)[tid];
    float4 o1;
    o1.x = g.x * dx * rstd + bb.x;
    o1.y = g.y * dy * rstd + bb.y;
    o1.z = g.z * dz * rstd + bb.z;
    o1.w = g.w * dw * rstd + bb.w;
    ((float4*)(x1 + row * (long)DM))[tid] = o1;

    float s2 = o1.x + o1.y + o1.z + o1.w;
    red[tid] = s2; __syncthreads();
    for (int o = 128; o > 0; o >>= 1) { if (tid < o) red[tid] += red[tid+o]; __syncthreads(); }
    float m2 = red[0] * (1.f/1024.f); __syncthreads();
    float ex = o1.x-m2, ey = o1.y-m2, ez = o1.z-m2, ew = o1.w-m2;
    red[tid] = ex*ex + ey*ey + ez*ez + ew*ew; __syncthreads();
    for (int o = 128; o > 0; o >>= 1) { if (tid < o) red[tid] += red[tid+o]; __syncthreads(); }
    float rstd2 = rsqrtf(red[0] * (1.f/1024.f) + 1e-5f); __syncthreads();

    float4 gg = ((const float4*)g0)[tid];
    float4 b2v = ((const float4*)b0)[tid];
    float4 o2;
    o2.x = gg.x * ex * rstd2 + b2v.x;
    o2.y = gg.y * ey * rstd2 + b2v.y;
    o2.z = gg.z * ez * rstd2 + b2v.z;
    o2.w = gg.w * ew * rstd2 + b2v.w;
    ((float4*)(h + row * (long)DM))[tid] = o2;
}

// ---------------- single LayerNorm (final y) ----------------
__global__ void final_ln_kernel(const float* __restrict__ z,
    const float* __restrict__ g, const float* __restrict__ b,
    float* __restrict__ y)
{
    long row = blockIdx.x;
    int tid = threadIdx.x;
    __shared__ float red[256];
    float4 v = ((const float4*)(z + row * (long)DM))[tid];
    red[tid] = v.x + v.y + v.z + v.w; __syncthreads();
    for (int o = 128; o > 0; o >>= 1) { if (tid < o) red[tid] += red[tid+o]; __syncthreads(); }
    float m = red[0] * (1.f/1024.f); __syncthreads();
    float dx = v.x-m, dy = v.y-m, dz = v.z-m, dw = v.w-m;
    red[tid] = dx*dx + dy*dy + dz*dz + dw*dw; __syncthreads();
    for (int o = 128; o > 0; o >>= 1) { if (tid < o) red[tid] += red[tid+o]; __syncthreads(); }
    float rstd = rsqrtf(red[0] * (1.f/1024.f) + 1e-5f);

    float4 gv = ((const float4*)g)[tid];
    float4 bv = ((const float4*)b)[tid];
    float4 o;
    o.x = gv.x * dx * rstd + bv.x;
    o.y = gv.y * dy * rstd + bv.y;
    o.z = gv.z * dz * rstd + bv.z;
    o.w = gv.w * dw * rstd + bv.w;
    ((float4*)(y + row * (long)DM))[tid] = o;
}

// ---------------- write path: slot logits + softmax + gate -> p ----------------
__global__ void slot_kernel(const float* __restrict__ wproj, const float* __restrict__ cache,
                            const float* __restrict__ wgate, float* __restrict__ p)
{
    int blk = blockIdx.x;
    int b = blk >> 8;
    int t = blk & 255;
    int k = threadIdx.x;
    const float4* wp = (const float4*)(wproj + ((long)b * TT + t) * DCC);
    const float4* lr = (const float4*)(cache + ((long)b * MCACHE + LAYER_OFF + k) * DCC);
    float dot = 0.f;
    #pragma unroll 8
    for (int c = 0; c < 128; c++) {
        float4 a = wp[c], w = lr[c];
        dot += a.x*w.x + a.y*w.y + a.z*w.z + a.w*w.w;
    }
    float logit = dot * SCALE_DC;
    __shared__ float red[64];
    red[k] = logit; __syncthreads();
    for (int o = 32; o > 0; o >>= 1) { if (k < o) red[k] = fmaxf(red[k], red[k+o]); __syncthreads(); }
    float m = red[0]; __syncthreads();
    float e = expf(logit - m);
    red[k] = e; __syncthreads();
    for (int o = 32; o > 0; o >>= 1) { if (k < o) red[k] += red[k+o]; __syncthreads(); }
    float val = e / red[0] * wgate[b * TT + t];
    p[((long)b * TT + t) * KSLOT + k] = val;
}

// ---------------- write path: out_cache[slice] += p^T vals ----------------
__global__ void update_kernel(const float* __restrict__ p, const float* __restrict__ vals,
                              float* __restrict__ out_cache)
{
    int blk = blockIdx.x;
    int b = blk >> 6;
    int k = blk & 63;
    int c0 = threadIdx.x * 2;
    float a0 = 0.f, a1 = 0.f;
    for (int t = 0; t < TT; t++) {
        float pv = p[((long)b * TT + t) * KSLOT + k];
        const float* vr = vals + ((long)b * TT + t) * DCC;
        a0 = fmaf(pv, vr[c0],     a0);
        a1 = fmaf(pv, vr[c0 + 1], a1);
    }
    float* oc = out_cache + ((long)b * MCACHE + LAYER_OFF + k) * DCC;
    oc[c0]     += a0;
    oc[c0 + 1] += a1;
}

// ---------------- launch ----------------
extern "C" void kernel_launch(void* const* d_in, const int* in_sizes, int n_in,
                              void* d_out_, int out_size)
{
    const float* x     = (const float*)d_in[0];
    const float* cache = (const float*)d_in[1];
    const float* Wq_r  = (const float*)d_in[2];
    const float* Wo_r  = (const float*)d_in[3];
    const float* Wg_r  = (const float*)d_in[4];
    const float* bg_r  = (const float*)d_in[5];
    const float* Wq    = (const float*)d_in[6];
    const float* Wk    = (const float*)d_in[7];
    const float* Wv    = (const float*)d_in[8];
    const float* Wo    = (const float*)d_in[9];
    const float* ln0g  = (const float*)d_in[10];
    const float* ln0b  = (const float*)d_in[11];
    const float* W1    = (const float*)d_in[12];
    const float* b1    = (const float*)d_in[13];
    const float* W2    = (const float*)d_in[14];
    const float* b2    = (const float*)d_in[15];
    const float* n1g   = (const float*)d_in[16];
    const float* n1b   = (const float*)d_in[17];
    const float* n2g   = (const float*)d_in[18];
    const float* n2b   = (const float*)d_in[19];
    /* d_in[20] = Ws : unused (write_scores dead in reference) */
    const float* Wgw   = (const float*)d_in[21];
    const float* bgw   = (const float*)d_in[22];
    const float* Wslot = (const float*)d_in[23];
    const float* Wvw   = (const float*)d_in[24];

    float* out       = (float*)d_out_;
    float* y_out     = out;
    float* cache_out = out + (size_t)NROWS * DM;

    float *p_qr, *p_scores, *p_ctx, *p_gate, *p_fused, *p_pq, *p_pk, *p_v;
    float *p_kv, *p_ksum, *p_kvpart, *p_kspart, *p_attn, *p_z, *p_x1, *p_h, *p_t1, *p_z2;
    float *p_wproj, *p_vals, *p_wgate, *p_p;
    cudaGetSymbolAddress((void**)&p_qr,     g_qr);
    cudaGetSymbolAddress((void**)&p_scores, g_scores);
    cudaGetSymbolAddress((void**)&p_ctx,    g_ctx);
    cudaGetSymbolAddress((void**)&p_gate,   g_gate);
    cudaGetSymbolAddress((void**)&p_fused,  g_fused);
    cudaGetSymbolAddress((void**)&p_pq,     g_pq);
    cudaGetSymbolAddress((void**)&p_pk,     g_pk);
    cudaGetSymbolAddress((void**)&p_v,      g_v);
    cudaGetSymbolAddress((void**)&p_kv,     g_kv);
    cudaGetSymbolAddress((void**)&p_ksum,   g_ksum);
    cudaGetSymbolAddress((void**)&p_kvpart, g_kvpart);
    cudaGetSymbolAddress((void**)&p_kspart, g_kspart);
    cudaGetSymbolAddress((void**)&p_attn,   g_attn);
    cudaGetSymbolAddress((void**)&p_z,      g_z);
    cudaGetSymbolAddress((void**)&p_x1,     g_x1);
    cudaGetSymbolAddress((void**)&p_h,      g_h);
    cudaGetSymbolAddress((void**)&p_t1,     g_t1);
    cudaGetSymbolAddress((void**)&p_z2,     g_z2);
    cudaGetSymbolAddress((void**)&p_wproj,  g_wproj);
    cudaGetSymbolAddress((void**)&p_vals,   g_vals);
    cudaGetSymbolAddress((void**)&p_wgate,  g_wgate);
    cudaGetSymbolAddress((void**)&p_p,      g_p);

    const long ZL = 0;

    // dynamic-smem sizes for the pipelined GEMM
    const int SM_NN = (2*ASIZE + 2*BKK*BSTRIDE) * (int)sizeof(float);  // 75776
    const int SM_TB = (2*ASIZE + 2*BN*ASTRIDE)  * (int)sizeof(float);  // 81920
    cudaFuncSetAttribute(tgemm_kernel<EPI_NONE,false>,     cudaFuncAttributeMaxDynamicSharedMemorySize, SM_NN);
    cudaFuncSetAttribute(tgemm_kernel<EPI_NONE,true>,      cudaFuncAttributeMaxDynamicSharedMemorySize, SM_TB);
    cudaFuncSetAttribute(tgemm_kernel<EPI_GATEADD,false>,  cudaFuncAttributeMaxDynamicSharedMemorySize, SM_NN);
    cudaFuncSetAttribute(tgemm_kernel<EPI_ELU1,false>,     cudaFuncAttributeMaxDynamicSharedMemorySize, SM_NN);
    cudaFuncSetAttribute(tgemm_kernel<EPI_ADD,false>,      cudaFuncAttributeMaxDynamicSharedMemorySize, SM_NN);
    cudaFuncSetAttribute(tgemm_kernel<EPI_BIAS_GELU,false>,cudaFuncAttributeMaxDynamicSharedMemorySize, SM_NN);
    cudaFuncSetAttribute(tgemm_kernel<EPI_BIAS_ADD,false>, cudaFuncAttributeMaxDynamicSharedMemorySize, SM_NN);

    // read gate: sigmoid(x @ Wg_r + bg_r)
    rowgate_kernel<<<NROWS, 256>>>(x, ZL, NROWS, Wg_r, bg_r, p_gate);

    // q_r = x @ Wq_r          [16384 x 512]
    tgemm_kernel<EPI_NONE,false><<<dim3(DCC/BN, NROWS/BM, 1), 256, SM_NN>>>(
        x, Wq_r, p_qr, NROWS, DCC, DM, ZL, ZL, ZL, nullptr, nullptr, ZL, nullptr);

    // scores = q_r @ cache^T  (batched NT)  [4 x 4096 x 768]
    tgemm_kernel<EPI_NONE,true><<<dim3(MCACHE/BN, SS/BM, BB), 256, SM_TB>>>(
        p_qr, cache, p_scores, SS, MCACHE, DCC,
        (long)SS*DCC, (long)MCACHE*DCC, (long)SS*MCACHE, nullptr, nullptr, ZL, nullptr);

    // softmax(scores / sqrt(DC))
    softmax768_kernel<<<NROWS, 256>>>(p_scores);

    // ctx = attn @ cache      (batched NN)  [4 x 4096 x 512]
    tgemm_kernel<EPI_NONE,false><<<dim3(DCC/BN, SS/BM, BB), 256, SM_NN>>>(
        p_scores, cache, p_ctx, SS, DCC, MCACHE,
        (long)SS*MCACHE, (long)MCACHE*DCC, (long)SS*DCC, nullptr, nullptr, ZL, nullptr);

    // fused = x + gate * (ctx @ Wo_r)
    tgemm_kernel<EPI_GATEADD,false><<<dim3(DM/BN, NROWS/BM, 1), 256, SM_NN>>>(
        p_ctx, Wo_r, p_fused, NROWS, DM, DCC, ZL, ZL, ZL, nullptr, x, ZL, p_gate);

    // pq = elu(fused @ Wq)+1, pk = elu(fused @ Wk)+1, v = fused @ Wv
    tgemm_kernel<EPI_ELU1,false><<<dim3(DM/BN, NROWS/BM, 1), 256, SM_NN>>>(
        p_fused, Wq, p_pq, NROWS, DM, DM, ZL, ZL, ZL, nullptr, nullptr, ZL, nullptr);
    tgemm_kernel<EPI_ELU1,false><<<dim3(DM/BN, NROWS/BM, 1), 256, SM_NN>>>(
        p_fused, Wk, p_pk, NROWS, DM, DM, ZL, ZL, ZL, nullptr, nullptr, ZL, nullptr);
    tgemm_kernel<EPI_NONE,false><<<dim3(DM/BN, NROWS/BM, 1), 256, SM_NN>>>(
        p_fused, Wv, p_v, NROWS, DM, DM, ZL, ZL, ZL, nullptr, nullptr, ZL, nullptr);

    // linear attention (kv split 8-way over sequence, then reduce)
    kvpart_kernel<<<dim3(BB*HH, KVCH), 256>>>(p_pk, p_v, p_kvpart, p_kspart);
    kvreduce_kernel<<<BB*HH, 256>>>(p_kvpart, p_kspart, p_kv, p_ksum);
    numden_kernel<<<dim3(BB*HH, SS/128), 256>>>(p_pq, p_kv, p_ksum, p_attn);

    // z = fused + attn @ Wo
    tgemm_kernel<EPI_ADD,false><<<dim3(DM/BN, NROWS/BM, 1), 256, SM_NN>>>(
        p_attn, Wo, p_z, NROWS, DM, DM, ZL, ZL, ZL, nullptr, p_fused, ZL, nullptr);

    // x1 = LN(z; n1), h = LN(x1; ln0)
    double_ln_kernel<<<NROWS, 256>>>(p_z, n1g, n1b, ln0g, ln0b, p_x1, p_h);

    // t1 = gelu(h @ W1 + b1)
    tgemm_kernel<EPI_BIAS_GELU,false><<<dim3(DFF/BN, NROWS/BM, 1), 256, SM_NN>>>(
        p_h, W1, p_t1, NROWS, DFF, DM, ZL, ZL, ZL, b1, nullptr, ZL, nullptr);

    // z2 = x1 + t1 @ W2 + b2
    tgemm_kernel<EPI_BIAS_ADD,false><<<dim3(DM/BN, NROWS/BM, 1), 256, SM_NN>>>(
        p_t1, W2, p_z2, NROWS, DM, DFF, ZL, ZL, ZL, b2, p_x1, ZL, nullptr);

    // y = LN(z2; n2)  -> straight into d_out
    final_ln_kernel<<<NROWS, 256>>>(p_z2, n2g, n2b, y_out);

    // ---- write path on wc = y[:, :256, :] ----
    tgemm_kernel<EPI_NONE,false><<<dim3(DCC/BN, TT/BM, BB), 256, SM_NN>>>(
        y_out, Wslot, p_wproj, TT, DCC, DM,
        (long)SS*DM, ZL, (long)TT*DCC, nullptr, nullptr, ZL, nullptr);
    tgemm_kernel<EPI_NONE,false><<<dim3(DCC/BN, TT/BM, BB), 256, SM_NN>>>(
        y_out, Wvw, p_vals, TT, DCC, DM,
        (long)SS*DM, ZL, (long)TT*DCC, nullptr, nullptr, ZL, nullptr);

    // write gate
    rowgate_kernel<<<BB*TT, 256>>>(y_out, (long)SS*DM, TT, Wgw, bgw, p_wgate);

    // slot probs * gate
    slot_kernel<<<BB*TT, 64>>>(p_wproj, cache, p_wgate, p_p);

    // new_cache = cache; new_cache[:, layer slice] += p^T vals
    cudaMemcpyAsync(cache_out, cache, (size_t)BB*MCACHE*DCC*sizeof(float),
                    cudaMemcpyDeviceToDevice, 0);
    update_kernel<<<BB*KSLOT, 256>>>(p_p, p_vals, cache_out);
}

// round 14
// speedup vs baseline: 3.4614x; 1.0310x over previous
#include <cuda_runtime.h>
#include <math.h>
#include <stdint.h>

// ---------------- problem constants ----------------
#define BB      4
#define SS      4096
#define DM      1024
#define HH      16
#define HDIM    64
#define DCC     512
#define KSLOT   64
#define MCACHE  768          // L*K = 12*64
#define TT      256          // min(S, 4K)
#define DFF     4096
#define LAYER_OFF 192        // LAYER*K = 3*64
#define NROWS   (BB*SS)      // 16384
#define SCALE_DC 0.044194173824159216f   // 1/sqrt(512)
#define KVCH    8            // kv split chunks

// ---------------- scratch (static device memory; allocation-free) ----------------
__device__ float g_qr    [(size_t)NROWS*DCC];
__device__ float g_scores[(size_t)NROWS*MCACHE];
__device__ float g_ctx   [(size_t)NROWS*DCC];
__device__ float g_gate  [(size_t)NROWS];
__device__ float g_fused [(size_t)NROWS*DM];
__device__ float g_pq    [(size_t)NROWS*DM];
__device__ float g_pk    [(size_t)NROWS*DM];
__device__ float g_v     [(size_t)NROWS*DM];
__device__ float g_kv    [(size_t)BB*HH*HDIM*HDIM];
__device__ float g_ksum  [(size_t)BB*HH*HDIM];
__device__ float g_kvpart[(size_t)KVCH*BB*HH*HDIM*HDIM];
__device__ float g_kspart[(size_t)KVCH*BB*HH*HDIM];
__device__ float g_attn  [(size_t)NROWS*DM];
__device__ float g_z     [(size_t)NROWS*DM];
__device__ float g_x1    [(size_t)NROWS*DM];
__device__ float g_h     [(size_t)NROWS*DM];
__device__ float g_t1    [(size_t)NROWS*DFF];
__device__ float g_z2    [(size_t)NROWS*DM];
__device__ float g_wproj [(size_t)BB*TT*DCC];
__device__ float g_vals  [(size_t)BB*TT*DCC];
__device__ float g_wgate [(size_t)BB*TT];
__device__ float g_p     [(size_t)BB*TT*KSLOT];

// ---------------- TF32 tensor-core GEMM: 128x128x32, 8 warps, cp.async 2-stage ----------------
// Operands fed as RAW fp32 bits (tf32-truncate mode): HW reads the 19 tf32 bits,
// removing all CVT instructions from the mainloop (issue-bound fix).
#define BM 128
#define BN 128
#define BKK 32
#define ASTRIDE 40    // BKK + 8  -> conflict-free STS.128 and fragment LDS
#define BSTRIDE 136   // BN  + 8  -> conflict-free STS.128 and fragment LDS
#define ASIZE (BM*ASTRIDE)                 // floats per A stage = 5120

enum { EPI_NONE=0, EPI_ELU1=1, EPI_GATEADD=2, EPI_ADD=3, EPI_BIAS_GELU=4, EPI_BIAS_ADD=5 };

__device__ __forceinline__ void mma_tf32(float* c, const uint32_t* a, const uint32_t* b) {
    asm("mma.sync.aligned.m16n8k8.row.col.f32.tf32.tf32.f32 "
        "{%0,%1,%2,%3}, {%4,%5,%6,%7}, {%8,%9}, {%0,%1,%2,%3};"
        : "+f"(c[0]), "+f"(c[1]), "+f"(c[2]), "+f"(c[3])
        : "r"(a[0]), "r"(a[1]), "r"(a[2]), "r"(a[3]), "r"(b[0]), "r"(b[1]));
}

__device__ __forceinline__ void cp_async16(float* smem_dst, const float* gsrc) {
    uint32_t s = (uint32_t)__cvta_generic_to_shared(smem_dst);
    asm volatile("cp.async.cg.shared.global [%0], [%1], 16;" :: "r"(s), "l"(gsrc));
}

template<int EPI, bool TB>
__global__ __launch_bounds__(256, 2) void tgemm_kernel(
    const float* __restrict__ A, const float* __restrict__ B, float* __restrict__ C,
    int M, int N, int K,
    long sA, long sB, long sC,
    const float* __restrict__ bias,
    const float* __restrict__ add, long sAdd,
    const float* __restrict__ gate)
{
    extern __shared__ float smem[];
    const int BSIZE = TB ? (BN * ASTRIDE) : (BKK * BSTRIDE);
    float* As = smem;                       // [2][ASIZE]
    float* Bs = smem + 2 * ASIZE;           // [2][BSIZE]

    const int bz = blockIdx.z;
    A += (long)bz * sA;
    B += (long)bz * sB;
    C += (long)bz * sC;
    if (EPI==EPI_GATEADD || EPI==EPI_ADD || EPI==EPI_BIAS_ADD) add += (long)bz * sAdd;

    const long bm = (long)blockIdx.y * BM;
    const long bn = (long)blockIdx.x * BN;
    const int tid  = threadIdx.x;
    const int lane = tid & 31;
    const int warp = tid >> 5;
    const int wm = warp & 1;        // 2 warps along M -> 128
    const int wn = warp >> 1;       // 4 warps along N -> 128
    const int g  = lane >> 2;       // 0..7
    const int t  = lane & 3;        // 0..3

    // per-thread load coordinates (same each tile)
    const int arow[4] = { (0*256+tid)>>3, (1*256+tid)>>3, (2*256+tid)>>3, (3*256+tid)>>3 };
    const int ac4 = (tid & 7) * 4;

    float acc[4][4][4];
    #pragma unroll
    for (int i = 0; i < 4; i++)
        #pragma unroll
        for (int j = 0; j < 4; j++) {
            acc[i][j][0]=0.f; acc[i][j][1]=0.f; acc[i][j][2]=0.f; acc[i][j][3]=0.f;
        }

    const int KT = K / BKK;

    // ---- tile loader (cp.async, 16B granules) ----
    auto load_tiles = [&](int kt, int stage) {
        const int k0 = kt * BKK;
        float* as = As + stage * ASIZE;
        float* bs = Bs + stage * BSIZE;
        #pragma unroll
        for (int it = 0; it < 4; it++) {
            int row = arow[it];
            cp_async16(as + row * ASTRIDE + ac4, A + (bm + row) * (long)K + k0 + ac4);
        }
        if (TB) {
            #pragma unroll
            for (int it = 0; it < 4; it++) {
                int row = arow[it];
                cp_async16(bs + row * ASTRIDE + ac4, B + (bn + row) * (long)K + k0 + ac4);
            }
        } else {
            #pragma unroll
            for (int it = 0; it < 4; it++) {
                int idx = it * 256 + tid;
                int kk = idx >> 5;
                int n4 = (idx & 31) * 4;
                cp_async16(bs + kk * BSTRIDE + n4, B + (long)(k0 + kk) * N + bn + n4);
            }
        }
    };

    // prologue: stage 0
    load_tiles(0, 0);
    asm volatile("cp.async.commit_group;");

    for (int kt = 0; kt < KT; kt++) {
        const int buf = kt & 1;
        if (kt + 1 < KT) {
            load_tiles(kt + 1, buf ^ 1);
            asm volatile("cp.async.commit_group;");
            asm volatile("cp.async.wait_group 1;");
        } else {
            asm volatile("cp.async.wait_group 0;");
        }
        __syncthreads();

        // raw fp32 bits -> tf32 truncate (no CVT instructions)
        const uint32_t* as = (const uint32_t*)(As + buf * ASIZE);
        const uint32_t* bs = (const uint32_t*)(Bs + buf * BSIZE);

        #pragma unroll
        for (int ks = 0; ks < 4; ks++) {
            const int kk = ks * 8;
            uint32_t a[4][4], b[4][2];
            #pragma unroll
            for (int mf = 0; mf < 4; mf++) {
                int m0 = wm*64 + mf*16 + g;
                a[mf][0] = as[(m0    ) * ASTRIDE + kk + t    ];
                a[mf][1] = as[(m0 + 8) * ASTRIDE + kk + t    ];
                a[mf][2] = as[(m0    ) * ASTRIDE + kk + t + 4];
                a[mf][3] = as[(m0 + 8) * ASTRIDE + kk + t + 4];
            }
            #pragma unroll
            for (int nf = 0; nf < 4; nf++) {
                int n0 = wn*32 + nf*8 + g;
                if (TB) {
                    b[nf][0] = bs[n0 * ASTRIDE + kk + t    ];
                    b[nf][1] = bs[n0 * ASTRIDE + kk + t + 4];
                } else {
                    b[nf][0] = bs[(kk + t    ) * BSTRIDE + n0];
                    b[nf][1] = bs[(kk + t + 4) * BSTRIDE + n0];
                }
            }
            #pragma unroll
            for (int mf = 0; mf < 4; mf++)
                #pragma unroll
                for (int nf = 0; nf < 4; nf++)
                    mma_tf32(acc[mf][nf], a[mf], b[nf]);
        }
        __syncthreads();
    }

    // ---------------- epilogue ----------------
    #pragma unroll
    for (int mf = 0; mf < 4; mf++) {
        long r0 = bm + wm*64 + mf*16 + g;
        long r1 = r0 + 8;
        float g0 = 0.f, g1f = 0.f;
        if (EPI == EPI_GATEADD) { g0 = gate[r0]; g1f = gate[r1]; }
        #pragma unroll
        for (int nf = 0; nf < 4; nf++) {
            long c0 = bn + wn*32 + nf*8 + t*2;
            #pragma unroll
            for (int half = 0; half < 2; half++) {
                long row = half ? r1 : r0;
                float grow = half ? g1f : g0;
                float v0 = acc[mf][nf][half*2 + 0];
                float v1 = acc[mf][nf][half*2 + 1];
                float o0, o1;
                if (EPI == EPI_NONE) {
                    o0 = v0; o1 = v1;
                } else if (EPI == EPI_ELU1) {
                    o0 = (v0 > 0.f) ? (v0 + 1.f) : expf(v0);
                    o1 = (v1 > 0.f) ? (v1 + 1.f) : expf(v1);
                } else if (EPI == EPI_GATEADD) {
                    o0 = add[row * (long)N + c0    ] + grow * v0;
                    o1 = add[row * (long)N + c0 + 1] + grow * v1;
                } else if (EPI == EPI_ADD) {
                    o0 = v0 + add[row * (long)N + c0    ];
                    o1 = v1 + add[row * (long)N + c0 + 1];
                } else if (EPI == EPI_BIAS_GELU) {
                    float t0 = v0 + bias[c0], t1 = v1 + bias[c0 + 1];
                    o0 = 0.5f * t0 * (1.f + erff(t0 * 0.70710678118654752f));
                    o1 = 0.5f * t1 * (1.f + erff(t1 * 0.70710678118654752f));
                } else { // EPI_BIAS_ADD
                    o0 = v0 + bias[c0    ] + add[row * (long)N + c0    ];
                    o1 = v1 + bias[c0 + 1] + add[row * (long)N + c0 + 1];
                }
                float2 ov = make_float2(o0, o1);
                *(float2*)&C[row * (long)N + c0] = ov;
            }
        }
    }
}

// ---------------- row dot + sigmoid (read/write gates) ----------------
__global__ void rowgate_kernel(const float* __restrict__ X, long batchStride, int rowsPerBatch,
                               const float* __restrict__ W, const float* __restrict__ bsc,
                               float* __restrict__ out)
{
    int row = blockIdx.x;
    int b = row / rowsPerBatch;
    int t = row - b * rowsPerBatch;
    const float4* xr = (const float4*)(X + (long)b * batchStride + (long)t * DM);
    const float4* w4 = (const float4*)W;
    int tid = threadIdx.x;
    float4 a = xr[tid], w = w4[tid];
    float s = a.x*w.x + a.y*w.y + a.z*w.z + a.w*w.w;
    __shared__ float red[256];
    red[tid] = s; __syncthreads();
    for (int o = 128; o > 0; o >>= 1) { if (tid < o) red[tid] += red[tid + o]; __syncthreads(); }
    if (tid == 0) out[row] = 1.f / (1.f + expf(-(red[0] + bsc[0])));
}

// ---------------- softmax over 768 (with 1/sqrt(DC) scale) ----------------
__global__ void softmax768_kernel(float* __restrict__ s)
{
    long row = blockIdx.x;
    float* p = s + row * (long)MCACHE;
    int tid = threadIdx.x;
    __shared__ float red[256];
    float v0 = p[tid]       * SCALE_DC;
    float v1 = p[tid + 256] * SCALE_DC;
    float v2 = p[tid + 512] * SCALE_DC;
    float m = fmaxf(v0, fmaxf(v1, v2));
    red[tid] = m; __syncthreads();
    for (int o = 128; o > 0; o >>= 1) { if (tid < o) red[tid] = fmaxf(red[tid], red[tid+o]); __syncthreads(); }
    m = red[0]; __syncthreads();
    v0 = expf(v0 - m); v1 = expf(v1 - m); v2 = expf(v2 - m);
    red[tid] = v0 + v1 + v2; __syncthreads();
    for (int o = 128; o > 0; o >>= 1) { if (tid < o) red[tid] += red[tid+o]; __syncthreads(); }
    float inv = 1.f / red[0];
    p[tid] = v0 * inv; p[tid + 256] = v1 * inv; p[tid + 512] = v2 * inv;
}

// ---------------- linear attention: partial kv over a seq chunk ----------------
__global__ void kvpart_kernel(const float* __restrict__ pk, const float* __restrict__ v,
                              float* __restrict__ kvpart, float* __restrict__ kspart)
{
    int bh = blockIdx.x;
    int ch = blockIdx.y;
    int b = bh / HH, h = bh % HH;
    const long baseoff = ((long)b * SS) * DM + (long)h * HDIM;
    const int s_begin = ch * (SS / KVCH);
    const int s_end   = s_begin + (SS / KVCH);
    __shared__ float pks[32][64];
    __shared__ float vs[32][64];
    int tid = threadIdx.x;
    int d0 = (tid >> 4) * 4;
    int e0 = (tid & 15) * 4;
    float acc[4][4];
    #pragma unroll
    for (int i=0;i<4;i++) { acc[i][0]=0;acc[i][1]=0;acc[i][2]=0;acc[i][3]=0; }
    float ks[4] = {0,0,0,0};
    int f0 = tid * 2;

    for (int s0 = s_begin; s0 < s_end; s0 += 32) {
        #pragma unroll
        for (int i = 0; i < 2; i++) {
            int f = f0 + i;
            int r = f >> 4;
            int c = (f & 15) * 4;
            long gg = baseoff + (long)(s0 + r) * DM + c;
            *(float4*)&pks[r][c] = *(const float4*)(pk + gg);
            *(float4*)&vs[r][c]  = *(const float4*)(v  + gg);
        }
        __syncthreads();
        #pragma unroll 8
        for (int s = 0; s < 32; s++) {
            float4 pv = *(const float4*)&pks[s][d0];
            float4 vv = *(const float4*)&vs[s][e0];
            float pa[4] = {pv.x, pv.y, pv.z, pv.w};
            float va[4] = {vv.x, vv.y, vv.z, vv.w};
            #pragma unroll
            for (int i = 0; i < 4; i++)
                #pragma unroll
                for (int j = 0; j < 4; j++)
                    acc[i][j] = fmaf(pa[i], va[j], acc[i][j]);
            if (e0 == 0) {
                #pragma unroll
                for (int i = 0; i < 4; i++) ks[i] += pa[i];
            }
        }
        __syncthreads();
    }

    float* kvb = kvpart + ((long)ch * BB * HH + bh) * HDIM * HDIM;
    #pragma unroll
    for (int i = 0; i < 4; i++)
        #pragma unroll
        for (int j = 0; j < 4; j++)
            kvb[(d0 + i) * 64 + e0 + j] = acc[i][j];
    if (e0 == 0) {
        float* ksb = kspart + ((long)ch * BB * HH + bh) * HDIM;
        #pragma unroll
        for (int i = 0; i < 4; i++) ksb[d0 + i] = ks[i];
    }
}

__global__ void kvreduce_kernel(const float* __restrict__ kvpart, const float* __restrict__ kspart,
                                float* __restrict__ kvout, float* __restrict__ ksout)
{
    int bh = blockIdx.x;
    int tid = threadIdx.x;
    for (int i = tid; i < HDIM*HDIM; i += 256) {
        float s = 0.f;
        #pragma unroll
        for (int ch = 0; ch < KVCH; ch++)
            s += kvpart[((long)ch * BB * HH + bh) * HDIM * HDIM + i];
        kvout[(long)bh * HDIM * HDIM + i] = s;
    }
    if (tid < HDIM) {
        float s = 0.f;
        #pragma unroll
        for (int ch = 0; ch < KVCH; ch++)
            s += kspart[((long)ch * BB * HH + bh) * HDIM + tid];
        ksout[(long)bh * HDIM + tid] = s;
    }
}

// ---------------- linear attention: attn = (pq @ kv) / (pq·ksum + eps) ----------------
__global__ void numden_kernel(const float* __restrict__ pq, const float* __restrict__ kv,
                              const float* __restrict__ ksum, float* __restrict__ attn)
{
    int bh = blockIdx.x;
    int b = bh / HH, h = bh % HH;
    __shared__ float kvs[64*64];
    __shared__ float kss[64];
    int tid = threadIdx.x;
    {
        const float4* kvb = (const float4*)(kv + (long)bh * 4096);
        for (int i = tid; i < 1024; i += 256) ((float4*)kvs)[i] = kvb[i];
        if (tid < 16) ((float4*)kss)[tid] = ((const float4*)(ksum + (long)bh * 64))[tid];
    }
    __syncthreads();

    int srow = blockIdx.y * 128 + (tid >> 1);
    int e0 = (tid & 1) * 32;
    const float* qr = pq + ((long)b * SS + srow) * DM + (long)h * HDIM;
    float num[32];
    #pragma unroll
    for (int e = 0; e < 32; e++) num[e] = 0.f;
    float den = 0.f;

    #pragma unroll
    for (int d4 = 0; d4 < 16; d4++) {
        float4 qv = *(const float4*)(qr + d4 * 4);
        float qa[4] = {qv.x, qv.y, qv.z, qv.w};
        #pragma unroll
        for (int dd = 0; dd < 4; dd++) {
            int d = d4 * 4 + dd;
            den = fmaf(qa[dd], kss[d], den);
            const float* kr = &kvs[d * 64 + e0];
            #pragma unroll
            for (int e = 0; e < 32; e++) num[e] = fmaf(qa[dd], kr[e], num[e]);
        }
    }
    float inv = 1.f / (den + 1e-6f);
    float* o = attn + ((long)b * SS + srow) * DM + (long)h * HDIM + e0;
    #pragma unroll
    for (int e = 0; e < 32; e++) o[e] = num[e] * inv;
}

// ---------------- fused double LayerNorm: x1 = LN(z;n1), h = LN(x1;ln0) ----------------
__global__ void double_ln_kernel(const float* __restrict__ z,
    const float* __restrict__ g1, const float* __restrict__ b1,
    const float* __restrict__ g0, const float* __restrict__ b0,
    float* __restrict__ x1, float* __restrict__ h)
{
    long row = blockIdx.x;
    int tid = threadIdx.x;
    __shared__ float red[256];
    float4 v = ((const float4*)(z + row * (long)DM))[tid];

    float s = v.x + v.y + v.z + v.w;
    red[tid] = s; __syncthreads();
    for (int o = 128; o > 0; o >>= 1) { if (tid < o) red[tid] += red[tid+o]; __syncthreads(); }
    float m = red[0] * (1.f/1024.f); __syncthreads();
    float dx = v.x-m, dy = v.y-m, dz = v.z-m, dw = v.w-m;
    red[tid] = dx*dx + dy*dy + dz*dz + dw*dw; __syncthreads();
    for (int o = 128; o > 0; o >>= 1) { if (tid < o) red[tid] += red[tid+o]; __syncthreads(); }
    float rstd = rsqrtf(red[0] * (1.f/1024.f) + 1e-5f); __syncthreads();

    float4 g = ((const float4*)g1)[tid];
    float4 bb = ((const float4*)b1)[tid];
    float4 o1;
    o1.x = g.x * dx * rstd + bb.x;
    o1.y = g.y * dy * rstd + bb.y;
    o1.z = g.z * dz * rstd + bb.z;
    o1.w = g.w * dw * rstd + bb.w;
    ((float4*)(x1 + row * (long)DM))[tid] = o1;

    float s2 = o1.x + o1.y + o1.z + o1.w;
    red[tid] = s2; __syncthreads();
    for (int o = 128; o > 0; o >>= 1) { if (tid < o) red[tid] += red[tid+o]; __syncthreads(); }
    float m2 = red[0] * (1.f/1024.f); __syncthreads();
    float ex = o1.x-m2, ey = o1.y-m2, ez = o1.z-m2, ew = o1.w-m2;
    red[tid] = ex*ex + ey*ey + ez*ez + ew*ew; __syncthreads();
    for (int o = 128; o > 0; o >>= 1) { if (tid < o) red[tid] += red[tid+o]; __syncthreads(); }
    float rstd2 = rsqrtf(red[0] * (1.f/1024.f) + 1e-5f); __syncthreads();

    float4 gg = ((const float4*)g0)[tid];
    float4 b2v = ((const float4*)b0)[tid];
    float4 o2;
    o2.x = gg.x * ex * rstd2 + b2v.x;
    o2.y = gg.y * ey * rstd2 + b2v.y;
    o2.z = gg.z * ez * rstd2 + b2v.z;
    o2.w = gg.w * ew * rstd2 + b2v.w;
    ((float4*)(h + row * (long)DM))[tid] = o2;
}

// ---------------- single LayerNorm (final y) ----------------
__global__ void final_ln_kernel(const float* __restrict__ z,
    const float* __restrict__ g, const float* __restrict__ b,
    float* __restrict__ y)
{
    long row = blockIdx.x;
    int tid = threadIdx.x;
    __shared__ float red[256];
    float4 v = ((const float4*)(z + row * (long)DM))[tid];
    red[tid] = v.x + v.y + v.z + v.w; __syncthreads();
    for (int o = 128; o > 0; o >>= 1) { if (tid < o) red[tid] += red[tid+o]; __syncthreads(); }
    float m = red[0] * (1.f/1024.f); __syncthreads();
    float dx = v.x-m, dy = v.y-m, dz = v.z-m, dw = v.w-m;
    red[tid] = dx*dx + dy*dy + dz*dz + dw*dw; __syncthreads();
    for (int o = 128; o > 0; o >>= 1) { if (tid < o) red[tid] += red[tid+o]; __syncthreads(); }
    float rstd = rsqrtf(red[0] * (1.f/1024.f) + 1e-5f);

    float4 gv = ((const float4*)g)[tid];
    float4 bv = ((const float4*)b)[tid];
    float4 o;
    o.x = gv.x * dx * rstd + bv.x;
    o.y = gv.y * dy * rstd + bv.y;
    o.z = gv.z * dz * rstd + bv.z;
    o.w = gv.w * dw * rstd + bv.w;
    ((float4*)(y + row * (long)DM))[tid] = o;
}

// ---------------- write path: slot logits + softmax + gate -> p ----------------
__global__ void slot_kernel(const float* __restrict__ wproj, const float* __restrict__ cache,
                            const float* __restrict__ wgate, float* __restrict__ p)
{
    int blk = blockIdx.x;
    int b = blk >> 8;
    int t = blk & 255;
    int k = threadIdx.x;
    const float4* wp = (const float4*)(wproj + ((long)b * TT + t) * DCC);
    const float4* lr = (const float4*)(cache + ((long)b * MCACHE + LAYER_OFF + k) * DCC);
    float dot = 0.f;
    #pragma unroll 8
    for (int c = 0; c < 128; c++) {
        float4 a = wp[c], w = lr[c];
        dot += a.x*w.x + a.y*w.y + a.z*w.z + a.w*w.w;
    }
    float logit = dot * SCALE_DC;
    __shared__ float red[64];
    red[k] = logit; __syncthreads();
    for (int o = 32; o > 0; o >>= 1) { if (k < o) red[k] = fmaxf(red[k], red[k+o]); __syncthreads(); }
    float m = red[0]; __syncthreads();
    float e = expf(logit - m);
    red[k] = e; __syncthreads();
    for (int o = 32; o > 0; o >>= 1) { if (k < o) red[k] += red[k+o]; __syncthreads(); }
    float val = e / red[0] * wgate[b * TT + t];
    p[((long)b * TT + t) * KSLOT + k] = val;
}

// ---------------- write path: out_cache[slice] += p^T vals ----------------
__global__ void update_kernel(const float* __restrict__ p, const float* __restrict__ vals,
                              float* __restrict__ out_cache)
{
    int blk = blockIdx.x;
    int b = blk >> 6;
    int k = blk & 63;
    int c0 = threadIdx.x * 2;
    float a0 = 0.f, a1 = 0.f;
    for (int t = 0; t < TT; t++) {
        float pv = p[((long)b * TT + t) * KSLOT + k];
        const float* vr = vals + ((long)b * TT + t) * DCC;
        a0 = fmaf(pv, vr[c0],     a0);
        a1 = fmaf(pv, vr[c0 + 1], a1);
    }
    float* oc = out_cache + ((long)b * MCACHE + LAYER_OFF + k) * DCC;
    oc[c0]     += a0;
    oc[c0 + 1] += a1;
}

// ---------------- launch ----------------
extern "C" void kernel_launch(void* const* d_in, const int* in_sizes, int n_in,
                              void* d_out_, int out_size)
{
    const float* x     = (const float*)d_in[0];
    const float* cache = (const float*)d_in[1];
    const float* Wq_r  = (const float*)d_in[2];
    const float* Wo_r  = (const float*)d_in[3];
    const float* Wg_r  = (const float*)d_in[4];
    const float* bg_r  = (const float*)d_in[5];
    const float* Wq    = (const float*)d_in[6];
    const float* Wk    = (const float*)d_in[7];
    const float* Wv    = (const float*)d_in[8];
    const float* Wo    = (const float*)d_in[9];
    const float* ln0g  = (const float*)d_in[10];
    const float* ln0b  = (const float*)d_in[11];
    const float* W1    = (const float*)d_in[12];
    const float* b1    = (const float*)d_in[13];
    const float* W2    = (const float*)d_in[14];
    const float* b2    = (const float*)d_in[15];
    const float* n1g   = (const float*)d_in[16];
    const float* n1b   = (const float*)d_in[17];
    const float* n2g   = (const float*)d_in[18];
    const float* n2b   = (const float*)d_in[19];
    /* d_in[20] = Ws : unused (write_scores dead in reference) */
    const float* Wgw   = (const float*)d_in[21];
    const float* bgw   = (const float*)d_in[22];
    const float* Wslot = (const float*)d_in[23];
    const float* Wvw   = (const float*)d_in[24];

    float* out       = (float*)d_out_;
    float* y_out     = out;
    float* cache_out = out + (size_t)NROWS * DM;

    float *p_qr, *p_scores, *p_ctx, *p_gate, *p_fused, *p_pq, *p_pk, *p_v;
    float *p_kv, *p_ksum, *p_kvpart, *p_kspart, *p_attn, *p_z, *p_x1, *p_h, *p_t1, *p_z2;
    float *p_wproj, *p_vals, *p_wgate, *p_p;
    cudaGetSymbolAddress((void**)&p_qr,     g_qr);
    cudaGetSymbolAddress((void**)&p_scores, g_scores);
    cudaGetSymbolAddress((void**)&p_ctx,    g_ctx);
    cudaGetSymbolAddress((void**)&p_gate,   g_gate);
    cudaGetSymbolAddress((void**)&p_fused,  g_fused);
    cudaGetSymbolAddress((void**)&p_pq,     g_pq);
    cudaGetSymbolAddress((void**)&p_pk,     g_pk);
    cudaGetSymbolAddress((void**)&p_v,      g_v);
    cudaGetSymbolAddress((void**)&p_kv,     g_kv);
    cudaGetSymbolAddress((void**)&p_ksum,   g_ksum);
    cudaGetSymbolAddress((void**)&p_kvpart, g_kvpart);
    cudaGetSymbolAddress((void**)&p_kspart, g_kspart);
    cudaGetSymbolAddress((void**)&p_attn,   g_attn);
    cudaGetSymbolAddress((void**)&p_z,      g_z);
    cudaGetSymbolAddress((void**)&p_x1,     g_x1);
    cudaGetSymbolAddress((void**)&p_h,      g_h);
    cudaGetSymbolAddress((void**)&p_t1,     g_t1);
    cudaGetSymbolAddress((void**)&p_z2,     g_z2);
    cudaGetSymbolAddress((void**)&p_wproj,  g_wproj);
    cudaGetSymbolAddress((void**)&p_vals,   g_vals);
    cudaGetSymbolAddress((void**)&p_wgate,  g_wgate);
    cudaGetSymbolAddress((void**)&p_p,      g_p);

    const long ZL = 0;

    // dynamic-smem sizes for the pipelined GEMM
    const int SM_NN = (2*ASIZE + 2*BKK*BSTRIDE) * (int)sizeof(float);  // 75776
    const int SM_TB = (2*ASIZE + 2*BN*ASTRIDE)  * (int)sizeof(float);  // 81920
    cudaFuncSetAttribute(tgemm_kernel<EPI_NONE,false>,     cudaFuncAttributeMaxDynamicSharedMemorySize, SM_NN);
    cudaFuncSetAttribute(tgemm_kernel<EPI_NONE,true>,      cudaFuncAttributeMaxDynamicSharedMemorySize, SM_TB);
    cudaFuncSetAttribute(tgemm_kernel<EPI_GATEADD,false>,  cudaFuncAttributeMaxDynamicSharedMemorySize, SM_NN);
    cudaFuncSetAttribute(tgemm_kernel<EPI_ELU1,false>,     cudaFuncAttributeMaxDynamicSharedMemorySize, SM_NN);
    cudaFuncSetAttribute(tgemm_kernel<EPI_ADD,false>,      cudaFuncAttributeMaxDynamicSharedMemorySize, SM_NN);
    cudaFuncSetAttribute(tgemm_kernel<EPI_BIAS_GELU,false>,cudaFuncAttributeMaxDynamicSharedMemorySize, SM_NN);
    cudaFuncSetAttribute(tgemm_kernel<EPI_BIAS_ADD,false>, cudaFuncAttributeMaxDynamicSharedMemorySize, SM_NN);

    // read gate: sigmoid(x @ Wg_r + bg_r)
    rowgate_kernel<<<NROWS, 256>>>(x, ZL, NROWS, Wg_r, bg_r, p_gate);

    // q_r = x @ Wq_r          [16384 x 512]
    tgemm_kernel<EPI_NONE,false><<<dim3(DCC/BN, NROWS/BM, 1), 256, SM_NN>>>(
        x, Wq_r, p_qr, NROWS, DCC, DM, ZL, ZL, ZL, nullptr, nullptr, ZL, nullptr);

    // scores = q_r @ cache^T  (batched NT)  [4 x 4096 x 768]
    tgemm_kernel<EPI_NONE,true><<<dim3(MCACHE/BN, SS/BM, BB), 256, SM_TB>>>(
        p_qr, cache, p_scores, SS, MCACHE, DCC,
        (long)SS*DCC, (long)MCACHE*DCC, (long)SS*MCACHE, nullptr, nullptr, ZL, nullptr);

    // softmax(scores / sqrt(DC))
    softmax768_kernel<<<NROWS, 256>>>(p_scores);

    // ctx = attn @ cache      (batched NN)  [4 x 4096 x 512]
    tgemm_kernel<EPI_NONE,false><<<dim3(DCC/BN, SS/BM, BB), 256, SM_NN>>>(
        p_scores, cache, p_ctx, SS, DCC, MCACHE,
        (long)SS*MCACHE, (long)MCACHE*DCC, (long)SS*DCC, nullptr, nullptr, ZL, nullptr);

    // fused = x + gate * (ctx @ Wo_r)
    tgemm_kernel<EPI_GATEADD,false><<<dim3(DM/BN, NROWS/BM, 1), 256, SM_NN>>>(
        p_ctx, Wo_r, p_fused, NROWS, DM, DCC, ZL, ZL, ZL, nullptr, x, ZL, p_gate);

    // pq = elu(fused @ Wq)+1, pk = elu(fused @ Wk)+1, v = fused @ Wv
    tgemm_kernel<EPI_ELU1,false><<<dim3(DM/BN, NROWS/BM, 1), 256, SM_NN>>>(
        p_fused, Wq, p_pq, NROWS, DM, DM, ZL, ZL, ZL, nullptr, nullptr, ZL, nullptr);
    tgemm_kernel<EPI_ELU1,false><<<dim3(DM/BN, NROWS/BM, 1), 256, SM_NN>>>(
        p_fused, Wk, p_pk, NROWS, DM, DM, ZL, ZL, ZL, nullptr, nullptr, ZL, nullptr);
    tgemm_kernel<EPI_NONE,false><<<dim3(DM/BN, NROWS/BM, 1), 256, SM_NN>>>(
        p_fused, Wv, p_v, NROWS, DM, DM, ZL, ZL, ZL, nullptr, nullptr, ZL, nullptr);

    // linear attention (kv split 8-way over sequence, then reduce)
    kvpart_kernel<<<dim3(BB*HH, KVCH), 256>>>(p_pk, p_v, p_kvpart, p_kspart);
    kvreduce_kernel<<<BB*HH, 256>>>(p_kvpart, p_kspart, p_kv, p_ksum);
    numden_kernel<<<dim3(BB*HH, SS/128), 256>>>(p_pq, p_kv, p_ksum, p_attn);

    // z = fused + attn @ Wo
    tgemm_kernel<EPI_ADD,false><<<dim3(DM/BN, NROWS/BM, 1), 256, SM_NN>>>(
        p_attn, Wo, p_z, NROWS, DM, DM, ZL, ZL, ZL, nullptr, p_fused, ZL, nullptr);

    // x1 = LN(z; n1), h = LN(x1; ln0)
    double_ln_kernel<<<NROWS, 256>>>(p_z, n1g, n1b, ln0g, ln0b, p_x1, p_h);

    // t1 = gelu(h @ W1 + b1)
    tgemm_kernel<EPI_BIAS_GELU,false><<<dim3(DFF/BN, NROWS/BM, 1), 256, SM_NN>>>(
        p_h, W1, p_t1, NROWS, DFF, DM, ZL, ZL, ZL, b1, nullptr, ZL, nullptr);

    // z2 = x1 + t1 @ W2 + b2
    tgemm_kernel<EPI_BIAS_ADD,false><<<dim3(DM/BN, NROWS/BM, 1), 256, SM_NN>>>(
        p_t1, W2, p_z2, NROWS, DM, DFF, ZL, ZL, ZL, b2, p_x1, ZL, nullptr);

    // y = LN(z2; n2)  -> straight into d_out
    final_ln_kernel<<<NROWS, 256>>>(p_z2, n2g, n2b, y_out);

    // ---- write path on wc = y[:, :256, :] ----
    tgemm_kernel<EPI_NONE,false><<<dim3(DCC/BN, TT/BM, BB), 256, SM_NN>>>(
        y_out, Wslot, p_wproj, TT, DCC, DM,
        (long)SS*DM, ZL, (long)TT*DCC, nullptr, nullptr, ZL, nullptr);
    tgemm_kernel<EPI_NONE,false><<<dim3(DCC/BN, TT/BM, BB), 256, SM_NN>>>(
        y_out, Wvw, p_vals, TT, DCC, DM,
        (long)SS*DM, ZL, (long)TT*DCC, nullptr, nullptr, ZL, nullptr);

    // write gate
    rowgate_kernel<<<BB*TT, 256>>>(y_out, (long)SS*DM, TT, Wgw, bgw, p_wgate);

    // slot probs * gate
    slot_kernel<<<BB*TT, 64>>>(p_wproj, cache, p_wgate, p_p);

    // new_cache = cache; new_cache[:, layer slice] += p^T vals
    cudaMemcpyAsync(cache_out, cache, (size_t)BB*MCACHE*DCC*sizeof(float),
                    cudaMemcpyDeviceToDevice, 0);
    update_kernel<<<BB*KSLOT, 256>>>(p_p, p_vals, cache_out);
}